// round 12
// baseline (speedup 1.0000x reference)
#include <cuda_runtime.h>
#include <cuda_fp16.h>
#include <cstdint>
#include <cstddef>

#define S_LEN 4096
#define HID   4096
#define NQ    32
#define NKV   8
#define HD    128
#define HALF  64
#define GRP   4
#define QKV_N (NQ*HD + 2*NKV*HD)   /* 6144 */
#define ATT_SCALE 0.08838834764831845f
#define KP    (2*HID)              /* 8192: A = [hi | lo] fp16 */
#define KW    HID                  /* 4096: B = [hi] fp16, cycled twice */
#define KTILE 64
#define KITER (KP/KTILE)           /* 128 */

/* ---------------- scratch (device globals: allocation-free) -------------- */
__device__ float  g_qkv[(size_t)S_LEN * QKV_N];
__device__ __half g_qh [(size_t)NQ  * S_LEN * HD];
__device__ __half g_kh [(size_t)NKV * S_LEN * HD];
__device__ __half g_Ah [(size_t)S_LEN * KP];
__device__ __half g_Wq [(size_t)QKV_N * KW];
__device__ __half g_Wo [(size_t)HID   * KW];

/* ======================= small asm helpers =============================== */
__device__ __forceinline__ uint32_t smem_u32(const void* p) {
    uint32_t a;
    asm("{ .reg .u64 t; cvta.to.shared.u64 t, %1; cvt.u32.u64 %0, t; }"
        : "=r"(a) : "l"(p));
    return a;
}
__device__ __forceinline__ uint32_t sw128(uint32_t off) {   /* Swizzle<3,4,3> */
    return off ^ ((off >> 3) & 0x70);
}
__device__ __forceinline__ void cp_async16(uint32_t saddr, const void* gaddr) {
    asm volatile("cp.async.cg.shared.global [%0], [%1], 16;"
                 :: "r"(saddr), "l"(gaddr));
}
#define CP_COMMIT() asm volatile("cp.async.commit_group;" ::: "memory")
#define CP_WAIT(n)  asm volatile("cp.async.wait_group %0;" :: "n"(n) : "memory")

__device__ __forceinline__ void ldsm_x4(uint32_t* f, uint32_t addr) {
    asm volatile("ldmatrix.sync.aligned.m8n8.x4.shared.b16 {%0,%1,%2,%3}, [%4];"
                 : "=r"(f[0]), "=r"(f[1]), "=r"(f[2]), "=r"(f[3]) : "r"(addr));
}
__device__ __forceinline__ void mma16816(float* d, const uint32_t* a,
                                         uint32_t b0, uint32_t b1) {
    asm volatile("mma.sync.aligned.m16n8k16.row.col.f32.f16.f16.f32 "
                 "{%0,%1,%2,%3}, {%4,%5,%6,%7}, {%8,%9}, {%0,%1,%2,%3};"
                 : "+f"(d[0]), "+f"(d[1]), "+f"(d[2]), "+f"(d[3])
                 : "r"(a[0]), "r"(a[1]), "r"(a[2]), "r"(a[3]), "r"(b0), "r"(b1));
}
__device__ __forceinline__ uint32_t pack_h2(float x, float y) {
    __half2 h = __floats2half2_rn(x, y);
    return *(uint32_t*)&h;
}

/* ================= fp16 conversion kernels =============================== */
__global__ __launch_bounds__(256) void split_rows(const float* __restrict__ src,
                                                  __half* __restrict__ dst) {
    size_t idx = (size_t)blockIdx.x * 256 + threadIdx.x;
    int r = (int)(idx >> 12), k = (int)(idx & 4095);
    float x = src[idx];
    __half hi = __float2half_rn(x);
    __half lo = __float2half_rn(x - __half2float(hi));
    size_t base = (size_t)r * KP + k;
    dst[base]       = hi;
    dst[base + HID] = lo;
}
__global__ __launch_bounds__(256) void conv_wt(const float* __restrict__ src,
                                               __half* __restrict__ dst, int N) {
    __shared__ float t[32][33];
    int kb = blockIdx.x * 32, nb = blockIdx.y * 32;
    int tx = threadIdx.x, ty = threadIdx.y;
#pragma unroll
    for (int i = 0; i < 32; i += 8)
        t[ty + i][tx] = src[(size_t)(kb + ty + i) * N + nb + tx];
    __syncthreads();
#pragma unroll
    for (int i = 0; i < 32; i += 8) {
        int n = nb + ty + i, k = kb + tx;
        dst[(size_t)n * KW + k] = __float2half_rn(t[tx][ty + i]);
    }
}

/* ====== mma.sync fp16 GEMM: CTA 128x128, 4 warps (2x2), warp 64x64 ======= */
#define TILE_BYTES 16384

__global__ __launch_bounds__(128) void gemm_mma(const __half* __restrict__ A,
                                                const __half* __restrict__ B,
                                                float* __restrict__ C, int N) {
    extern __shared__ char smc[];
    const uint32_t smb = smem_u32(smc);
    const int tid  = threadIdx.x;
    const int lane = tid & 31;
    const int wid  = tid >> 5;
    const int wm   = wid & 1;          /* 0..1 : 64-row slab */
    const int wn   = wid >> 1;         /* 0..1 : 64-col slab */
    const int m0   = blockIdx.x * 128;
    const int n0   = blockIdx.y * 128;

    const uint32_t sA[2] = { smb,              smb + 2*TILE_BYTES };
    const uint32_t sB[2] = { smb + TILE_BYTES, smb + 3*TILE_BYTES };

    /* loaders: thread t owns full row t of A and of B (8 x 16B each) */
    const __half* gA = A + (size_t)(m0 + tid) * KP;
    const __half* gB = B + (size_t)(n0 + tid) * KW;
    uint32_t soff[8];
#pragma unroll
    for (int j = 0; j < 8; j++)
        soff[j] = sw128((uint32_t)tid * 128u + (uint32_t)j * 16u);

    float acc[4][8][4];
#pragma unroll
    for (int i = 0; i < 4; i++)
#pragma unroll
        for (int j = 0; j < 8; j++)
#pragma unroll
            for (int q = 0; q < 4; q++) acc[i][j][q] = 0.0f;

    const int arow = wm * 64 + (lane & 15);
    const int brow = wn * 64 + (lane & 15);
    const int kc   = lane >> 4;

#pragma unroll
    for (int p = 0; p < 2; p++) {
        const __half* pa = gA + (size_t)p * KTILE;
        const __half* pb = gB + (size_t)p * KTILE;
#pragma unroll
        for (int j = 0; j < 8; j++) {
            cp_async16(sA[p] + soff[j], pa + j * 8);
            cp_async16(sB[p] + soff[j], pb + j * 8);
        }
        CP_COMMIT();
    }

    for (int it = 0; it < KITER; ++it) {
        const int s = it & 1;
        if (it + 1 < KITER) CP_WAIT(1); else CP_WAIT(0);
        __syncthreads();

#pragma unroll
        for (int ks = 0; ks < 4; ks++) {
            uint32_t aF[4][4], bF[4][4];
            const uint32_t acol = (uint32_t)(ks * 2 + kc) * 16u;
#pragma unroll
            for (int mt = 0; mt < 4; mt++)
                ldsm_x4(aF[mt], sA[s] + sw128((uint32_t)(arow + mt * 16) * 128u + acol));
#pragma unroll
            for (int bn = 0; bn < 4; bn++)
                ldsm_x4(bF[bn], sB[s] + sw128((uint32_t)(brow + bn * 16) * 128u + acol));
#pragma unroll
            for (int mt = 0; mt < 4; mt++)
#pragma unroll
                for (int bn = 0; bn < 4; bn++) {
                    mma16816(acc[mt][bn * 2 + 0], aF[mt], bF[bn][0], bF[bn][2]);
                    mma16816(acc[mt][bn * 2 + 1], aF[mt], bF[bn][1], bF[bn][3]);
                }
        }
        __syncthreads();

        if (it + 2 < KITER) {
            const int sn = s;
            const __half* pa = gA + (size_t)(it + 2) * KTILE;
            const __half* pb = gB + (size_t)((it + 2) & 63) * KTILE;
#pragma unroll
            for (int j = 0; j < 8; j++) {
                cp_async16(sA[sn] + soff[j], pa + j * 8);
                cp_async16(sB[sn] + soff[j], pb + j * 8);
            }
            CP_COMMIT();
        }
    }

#pragma unroll
    for (int mt = 0; mt < 4; mt++) {
        const int row0 = m0 + wm * 64 + mt * 16 + (lane >> 2);
#pragma unroll
        for (int nt = 0; nt < 8; nt++) {
            const int col = n0 + wn * 64 + nt * 8 + (lane & 3) * 2;
            float2 lo = { acc[mt][nt][0], acc[mt][nt][1] };
            float2 hi = { acc[mt][nt][2], acc[mt][nt][3] };
            *(float2*)(C + (size_t)row0 * N + col)       = lo;
            *(float2*)(C + (size_t)(row0 + 8) * N + col) = hi;
        }
    }
}

/* ---------------- RoPE -> fp16 per-head Q/K layouts ---------------------- */
__global__ __launch_bounds__(256) void rope_split(const int* __restrict__ positions) {
    const int s = blockIdx.x;
    const float* row = g_qkv + (size_t)s * QKV_N;
    const float pos = (float)positions[s];
    const int tid = threadIdx.x;
    const float LN_THETA_OVER_HALF = 9.210340371976184f / 64.0f;

    for (int idx = tid; idx < NQ * HALF; idx += 256) {
        int h = idx >> 6, j = idx & 63;
        float inv = expf(-(float)j * LN_THETA_OVER_HALF);
        float f = pos * inv;
        float c = cosf(f), sn = sinf(f);
        float x1 = row[h * HD + j];
        float x2 = row[h * HD + HALF + j];
        __half* o = g_qh + ((size_t)h * S_LEN + s) * HD;
        o[j]        = __float2half_rn(x1 * c - x2 * sn);
        o[HALF + j] = __float2half_rn(x2 * c + x1 * sn);
    }
    for (int idx = tid; idx < NKV * HALF; idx += 256) {
        int h = idx >> 6, j = idx & 63;
        float inv = expf(-(float)j * LN_THETA_OVER_HALF);
        float f = pos * inv;
        float c = cosf(f), sn = sinf(f);
        const float* kr = row + NQ * HD;
        float x1 = kr[h * HD + j];
        float x2 = kr[h * HD + HALF + j];
        __half* o = g_kh + ((size_t)h * S_LEN + s) * HD;
        o[j]        = __float2half_rn(x1 * c - x2 * sn);
        o[HALF + j] = __float2half_rn(x2 * c + x1 * sn);
    }
}

/* ======== tensor-core flash attention: Br=128, Bc=64, causal, fp16 ======= */
#define AS_Q   0
#define AS_K   32768
#define AS_VH  (AS_K + 16384)
#define AS_KP  (AS_VH + 16384)
#define AS_TOT (AS_KP + 256)

__global__ __launch_bounds__(256) void attn_mma(const int* __restrict__ positions) {
    extern __shared__ char smc[];
    const uint32_t smb = smem_u32(smc);
    int* kp = (int*)(smc + AS_KP);

    const int h  = blockIdx.y;
    const int qt = 31 - blockIdx.x;
    const int g  = h / GRP;
    const int tid  = threadIdx.x;
    const int lane = tid & 31;
    const int w    = tid >> 5;
    const int kc   = lane >> 4;

    const __half* qg = g_qh + ((size_t)h * S_LEN + (size_t)qt * 128) * HD;
    for (int c = tid; c < 2048; c += 256) {
        int s = c >> 4, cc = c & 15;
        uint32_t dst = smb + AS_Q +
            sw128((uint32_t)(s * 2 + (cc >> 3)) * 128u + (uint32_t)(cc & 7) * 16u);
        cp_async16(dst, (const char*)qg + (size_t)c * 16);
    }
    CP_COMMIT();

    const int qr = qt * 128 + w * 16 + (lane >> 2);
    const int qpos0 = positions[qr];
    const int qpos1 = positions[qr + 8];

    float m_i[2] = { -1e30f, -1e30f };
    float l_i[2] = { 0.0f, 0.0f };
    float acc[16][4];
#pragma unroll
    for (int t = 0; t < 16; t++)
#pragma unroll
        for (int q = 0; q < 4; q++) acc[t][q] = 0.0f;

    CP_WAIT(0);
    __syncthreads();

    const int ntiles = 2 * qt + 2;
    for (int kt = 0; kt < ntiles; kt++) {
        __syncthreads();

        const __half* kg = g_kh + ((size_t)g * S_LEN + (size_t)kt * 64) * HD;
        for (int c = tid; c < 1024; c += 256) {
            int s = c >> 4, cc = c & 15;
            uint32_t dst = smb + AS_K +
                sw128((uint32_t)(s * 2 + (cc >> 3)) * 128u + (uint32_t)(cc & 7) * 16u);
            cp_async16(dst, (const char*)kg + (size_t)c * 16);
        }
        CP_COMMIT();

        {
            const float* vg = g_qkv + (size_t)(kt * 64) * QKV_N
                              + (NQ * HD + NKV * HD + g * HD);
            const int srow = tid >> 2;
            const int dq   = (tid & 3) * 32;
            const float4* vrow = (const float4*)(vg + (size_t)srow * QKV_N + dq);
#pragma unroll
            for (int q4 = 0; q4 < 8; q4++) {
                float4 v = vrow[q4];
                float e[4] = { v.x, v.y, v.z, v.w };
#pragma unroll
                for (int e4 = 0; e4 < 4; e4++) {
                    int d = dq + q4 * 4 + e4;
                    uint32_t off = sw128((uint32_t)d * 128u + (uint32_t)srow * 2u);
                    *(__half*)(smc + AS_VH + off) = __float2half_rn(e[e4]);
                }
            }
        }
        if (tid < 64) kp[tid] = positions[kt * 64 + tid];

        CP_WAIT(0);
        __syncthreads();

        float sc[8][4];
#pragma unroll
        for (int j = 0; j < 8; j++)
#pragma unroll
            for (int q = 0; q < 4; q++) sc[j][q] = 0.0f;

#pragma unroll
        for (int ks = 0; ks < 8; ks++) {
            const int cc = 2 * ks + kc;
            uint32_t aF[4];
            {
                int m = w * 16 + (lane & 15);
                ldsm_x4(aF, smb + AS_Q +
                    sw128((uint32_t)(m * 2 + (cc >> 3)) * 128u + (uint32_t)(cc & 7) * 16u));
            }
#pragma unroll
            for (int grp = 0; grp < 4; grp++) {
                uint32_t bF[4];
                int kv = grp * 16 + (lane & 15);
                ldsm_x4(bF, smb + AS_K +
                    sw128((uint32_t)(kv * 2 + (cc >> 3)) * 128u + (uint32_t)(cc & 7) * 16u));
                mma16816(sc[grp * 2 + 0], aF, bF[0], bF[2]);
                mma16816(sc[grp * 2 + 1], aF, bF[1], bF[3]);
            }
        }

#pragma unroll
        for (int j = 0; j < 8; j++) {
            int kcol = j * 8 + 2 * (lane & 3);
            int kp0 = kp[kcol], kp1 = kp[kcol + 1];
            float s0 = sc[j][0] * ATT_SCALE, s1 = sc[j][1] * ATT_SCALE;
            float s2 = sc[j][2] * ATT_SCALE, s3 = sc[j][3] * ATT_SCALE;
            sc[j][0] = (qpos0 >= kp0) ? s0 : -1e30f;
            sc[j][1] = (qpos0 >= kp1) ? s1 : -1e30f;
            sc[j][2] = (qpos1 >= kp0) ? s2 : -1e30f;
            sc[j][3] = (qpos1 >= kp1) ? s3 : -1e30f;
        }

        float mt0 = -1e30f, mt1 = -1e30f;
#pragma unroll
        for (int j = 0; j < 8; j++) {
            mt0 = fmaxf(mt0, fmaxf(sc[j][0], sc[j][1]));
            mt1 = fmaxf(mt1, fmaxf(sc[j][2], sc[j][3]));
        }
        mt0 = fmaxf(mt0, __shfl_xor_sync(0xffffffffu, mt0, 1));
        mt0 = fmaxf(mt0, __shfl_xor_sync(0xffffffffu, mt0, 2));
        mt1 = fmaxf(mt1, __shfl_xor_sync(0xffffffffu, mt1, 1));
        mt1 = fmaxf(mt1, __shfl_xor_sync(0xffffffffu, mt1, 2));

        float mn0 = fmaxf(m_i[0], mt0), mn1 = fmaxf(m_i[1], mt1);
        float al0 = __expf(m_i[0] - mn0), al1 = __expf(m_i[1] - mn1);
        m_i[0] = mn0; m_i[1] = mn1;

        float rs0 = 0.0f, rs1 = 0.0f;
#pragma unroll
        for (int j = 0; j < 8; j++) {
            sc[j][0] = __expf(sc[j][0] - mn0);
            sc[j][1] = __expf(sc[j][1] - mn0);
            sc[j][2] = __expf(sc[j][2] - mn1);
            sc[j][3] = __expf(sc[j][3] - mn1);
            rs0 += sc[j][0] + sc[j][1];
            rs1 += sc[j][2] + sc[j][3];
        }
        rs0 += __shfl_xor_sync(0xffffffffu, rs0, 1);
        rs0 += __shfl_xor_sync(0xffffffffu, rs0, 2);
        rs1 += __shfl_xor_sync(0xffffffffu, rs1, 1);
        rs1 += __shfl_xor_sync(0xffffffffu, rs1, 2);
        l_i[0] = l_i[0] * al0 + rs0;
        l_i[1] = l_i[1] * al1 + rs1;

#pragma unroll
        for (int t = 0; t < 16; t++) {
            acc[t][0] *= al0; acc[t][1] *= al0;
            acc[t][2] *= al1; acc[t][3] *= al1;
        }

        /* ---- PV: acc += (Phi + Plo) * Vh  (exact P x Vh) ---- */
#pragma unroll
        for (int ks = 0; ks < 4; ks++) {
            const int j0 = 2 * ks, j1 = 2 * ks + 1;
            uint32_t ahi[4], alo[4];
            ahi[0] = pack_h2(sc[j0][0], sc[j0][1]);
            ahi[1] = pack_h2(sc[j0][2], sc[j0][3]);
            ahi[2] = pack_h2(sc[j1][0], sc[j1][1]);
            ahi[3] = pack_h2(sc[j1][2], sc[j1][3]);
            {
                __half2* hp;
                hp = (__half2*)&ahi[0];
                alo[0] = pack_h2(sc[j0][0] - __half2float(hp->x),
                                 sc[j0][1] - __half2float(hp->y));
                hp = (__half2*)&ahi[1];
                alo[1] = pack_h2(sc[j0][2] - __half2float(hp->x),
                                 sc[j0][3] - __half2float(hp->y));
                hp = (__half2*)&ahi[2];
                alo[2] = pack_h2(sc[j1][0] - __half2float(hp->x),
                                 sc[j1][1] - __half2float(hp->y));
                hp = (__half2*)&ahi[3];
                alo[3] = pack_h2(sc[j1][2] - __half2float(hp->x),
                                 sc[j1][3] - __half2float(hp->y));
            }
            const uint32_t ccol = (uint32_t)(2 * ks + kc) * 16u;
#pragma unroll
            for (int grp = 0; grp < 8; grp++) {
                uint32_t vh[4];
                uint32_t roff = sw128((uint32_t)(grp * 16 + (lane & 15)) * 128u + ccol);
                ldsm_x4(vh, smb + AS_VH + roff);
                const int t0 = grp * 2, t1 = grp * 2 + 1;
                mma16816(acc[t0], ahi, vh[0], vh[2]);
                mma16816(acc[t1], ahi, vh[1], vh[3]);
                mma16816(acc[t0], alo, vh[0], vh[2]);
                mma16816(acc[t1], alo, vh[1], vh[3]);
            }
        }
    }

    /* ---- epilogue: normalize + write split-fp16 [hi|lo] into g_Ah ------- */
    float inv0 = 1.0f / l_i[0];
    float inv1 = 1.0f / l_i[1];
    const size_t base0 = (size_t)qr * KP;
    const size_t base1 = (size_t)(qr + 8) * KP;
#pragma unroll
    for (int t = 0; t < 16; t++) {
        int col = h * HD + t * 8 + (lane & 3) * 2;
        float o00 = acc[t][0] * inv0, o01 = acc[t][1] * inv0;
        float o10 = acc[t][2] * inv1, o11 = acc[t][3] * inv1;

        uint32_t h0 = pack_h2(o00, o01);
        __half2 hh0 = *(__half2*)&h0;
        uint32_t l0 = pack_h2(o00 - __half2float(hh0.x),
                              o01 - __half2float(hh0.y));
        uint32_t h1 = pack_h2(o10, o11);
        __half2 hh1 = *(__half2*)&h1;
        uint32_t l1 = pack_h2(o10 - __half2float(hh1.x),
                              o11 - __half2float(hh1.y));

        *(uint32_t*)(g_Ah + base0 + col)        = h0;
        *(uint32_t*)(g_Ah + base0 + HID + col)  = l0;
        *(uint32_t*)(g_Ah + base1 + col)        = h1;
        *(uint32_t*)(g_Ah + base1 + HID + col)  = l1;
    }
}

/* ------------------------------- launch ---------------------------------- */
extern "C" void kernel_launch(void* const* d_in, const int* in_sizes, int n_in,
                              void* d_out, int out_size) {
    const int*   positions = (const int*)  d_in[0];
    const float* hidden    = (const float*)d_in[1];
    const float* w_qkv     = (const float*)d_in[2];
    const float* w_o       = (const float*)d_in[3];
    float*       out       = (float*)d_out;
    (void)in_sizes; (void)n_in; (void)out_size;

    void *p_qkv = nullptr, *p_ah = nullptr, *p_wq = nullptr, *p_wo = nullptr;
    cudaGetSymbolAddress(&p_qkv, g_qkv);
    cudaGetSymbolAddress(&p_ah,  g_Ah);
    cudaGetSymbolAddress(&p_wq,  g_Wq);
    cudaGetSymbolAddress(&p_wo,  g_Wo);

    const int gemm_smem = 4 * TILE_BYTES;   /* 64 KB */
    cudaFuncSetAttribute(gemm_mma, cudaFuncAttributeMaxDynamicSharedMemorySize,
                         gemm_smem);
    cudaFuncSetAttribute(attn_mma, cudaFuncAttributeMaxDynamicSharedMemorySize,
                         AS_TOT);

    /* 0) fp16 conversions */
    split_rows<<<(S_LEN * HID) / 256, 256>>>(hidden, (__half*)p_ah);
    conv_wt<<<dim3(HID / 32, QKV_N / 32), dim3(32, 8)>>>(w_qkv, (__half*)p_wq, QKV_N);
    conv_wt<<<dim3(HID / 32, HID / 32), dim3(32, 8)>>>(w_o, (__half*)p_wo, HID);

    /* 1) QKV projection (tensor cores, split-fp16 2-term) */
    gemm_mma<<<dim3(S_LEN / 128, QKV_N / 128), 128, gemm_smem>>>(
        (const __half*)p_ah, (const __half*)p_wq, (float*)p_qkv, QKV_N);

    /* 2) RoPE -> fp16 Q/K */
    rope_split<<<S_LEN, 256>>>(positions);

    /* 3) tensor-core flash attention; epilogue emits split-fp16 into g_Ah */
    attn_mma<<<dim3(32, NQ), 256, AS_TOT>>>(positions);

    /* 4) output projection (tensor cores) */
    gemm_mma<<<dim3(S_LEN / 128, HID / 128), 128, gemm_smem>>>(
        (const __half*)p_ah, (const __half*)p_wo, out, HID);
}

// round 13
// speedup vs baseline: 1.3973x; 1.3973x over previous
#include <cuda_runtime.h>
#include <cuda_fp16.h>
#include <cstdint>
#include <cstddef>

#define S_LEN 4096
#define HID   4096
#define NQ    32
#define NKV   8
#define HD    128
#define HALF  64
#define GRP   4
#define QKV_N (NQ*HD + 2*NKV*HD)   /* 6144 */
#define ATT_SCALE 0.08838834764831845f
#define KP    (2*HID)              /* 8192: A = [hi | lo] fp16 */
#define KW    HID                  /* 4096: B = [hi] fp16, cycled twice */
#define KTILE 64
#define KITER (KP/KTILE)           /* 128 */

/* ---------------- scratch (device globals: allocation-free) -------------- */
__device__ float  g_qkv[(size_t)S_LEN * QKV_N];
__device__ __half g_qh [(size_t)NQ  * S_LEN * HD];   /* roped Q fp16 [h][s][d] */
__device__ __half g_kh [(size_t)NKV * S_LEN * HD];   /* roped K fp16 [g][s][d] */
__device__ __half g_vh [(size_t)NKV * HD * S_LEN];   /* V fp16 [g][d][s]       */
__device__ __half g_Ah [(size_t)S_LEN * KP];
__device__ __half g_Wq [(size_t)QKV_N * KW];
__device__ __half g_Wo [(size_t)HID   * KW];

/* ======================= small asm helpers =============================== */
__device__ __forceinline__ uint32_t smem_u32(const void* p) {
    uint32_t a;
    asm("{ .reg .u64 t; cvta.to.shared.u64 t, %1; cvt.u32.u64 %0, t; }"
        : "=r"(a) : "l"(p));
    return a;
}
__device__ __forceinline__ uint32_t sw128(uint32_t off) {   /* Swizzle<3,4,3> */
    return off ^ ((off >> 3) & 0x70);
}
__device__ __forceinline__ void cp_async16(uint32_t saddr, const void* gaddr) {
    asm volatile("cp.async.cg.shared.global [%0], [%1], 16;"
                 :: "r"(saddr), "l"(gaddr));
}
#define CP_COMMIT() asm volatile("cp.async.commit_group;" ::: "memory")
#define CP_WAIT(n)  asm volatile("cp.async.wait_group %0;" :: "n"(n) : "memory")

__device__ __forceinline__ void ldsm_x4(uint32_t* f, uint32_t addr) {
    asm volatile("ldmatrix.sync.aligned.m8n8.x4.shared.b16 {%0,%1,%2,%3}, [%4];"
                 : "=r"(f[0]), "=r"(f[1]), "=r"(f[2]), "=r"(f[3]) : "r"(addr));
}
__device__ __forceinline__ void mma16816(float* d, const uint32_t* a,
                                         uint32_t b0, uint32_t b1) {
    asm volatile("mma.sync.aligned.m16n8k16.row.col.f32.f16.f16.f32 "
                 "{%0,%1,%2,%3}, {%4,%5,%6,%7}, {%8,%9}, {%0,%1,%2,%3};"
                 : "+f"(d[0]), "+f"(d[1]), "+f"(d[2]), "+f"(d[3])
                 : "r"(a[0]), "r"(a[1]), "r"(a[2]), "r"(a[3]), "r"(b0), "r"(b1));
}
__device__ __forceinline__ uint32_t pack_h2(float x, float y) {
    __half2 h = __floats2half2_rn(x, y);
    return *(uint32_t*)&h;
}

/* ================= fp16 conversion kernels =============================== */
__global__ __launch_bounds__(256) void split_rows(const float* __restrict__ src,
                                                  __half* __restrict__ dst) {
    size_t idx = (size_t)blockIdx.x * 256 + threadIdx.x;
    int r = (int)(idx >> 12), k = (int)(idx & 4095);
    float x = src[idx];
    __half hi = __float2half_rn(x);
    __half lo = __float2half_rn(x - __half2float(hi));
    size_t base = (size_t)r * KP + k;
    dst[base]       = hi;
    dst[base + HID] = lo;
}
__global__ __launch_bounds__(256) void conv_wt(const float* __restrict__ src,
                                               __half* __restrict__ dst, int N) {
    __shared__ float t[32][33];
    int kb = blockIdx.x * 32, nb = blockIdx.y * 32;
    int tx = threadIdx.x, ty = threadIdx.y;
#pragma unroll
    for (int i = 0; i < 32; i += 8)
        t[ty + i][tx] = src[(size_t)(kb + ty + i) * N + nb + tx];
    __syncthreads();
#pragma unroll
    for (int i = 0; i < 32; i += 8) {
        int n = nb + ty + i, k = kb + tx;
        dst[(size_t)n * KW + k] = __float2half_rn(t[tx][ty + i]);
    }
}

/* ========== mma.sync fp16 GEMM (R11-validated shape, 256 thr) ============ */
#define TILE_BYTES 16384

__global__ __launch_bounds__(256) void gemm_mma(const __half* __restrict__ A,
                                                const __half* __restrict__ B,
                                                float* __restrict__ C, int N) {
    extern __shared__ char smc[];
    const uint32_t smb = smem_u32(smc);
    const int tid  = threadIdx.x;
    const int lane = tid & 31;
    const int wid  = tid >> 5;
    const int wm   = wid & 1;
    const int wn   = wid >> 1;
    const int m0   = blockIdx.x * 128;
    const int n0   = blockIdx.y * 128;

    const uint32_t sA[2] = { smb,              smb + 2*TILE_BYTES };
    const uint32_t sB[2] = { smb + TILE_BYTES, smb + 3*TILE_BYTES };

    const int r    = tid >> 1;
    const int halfc= tid & 1;
    const __half* gA = A + (size_t)(m0 + r) * KP + halfc * 32;
    const __half* gB = B + (size_t)(n0 + r) * KW + halfc * 32;
    const uint32_t soff[4] = {
        sw128((uint32_t)r * 128u + (uint32_t)(halfc * 4 + 0) * 16u),
        sw128((uint32_t)r * 128u + (uint32_t)(halfc * 4 + 1) * 16u),
        sw128((uint32_t)r * 128u + (uint32_t)(halfc * 4 + 2) * 16u),
        sw128((uint32_t)r * 128u + (uint32_t)(halfc * 4 + 3) * 16u) };

    float acc[4][4][4];
#pragma unroll
    for (int i = 0; i < 4; i++)
#pragma unroll
        for (int j = 0; j < 4; j++)
#pragma unroll
            for (int q = 0; q < 4; q++) acc[i][j][q] = 0.0f;

    const int arow = wm * 64 + (lane & 15);
    const int brow = wn * 32 + (lane & 15);
    const int kc   = lane >> 4;

#pragma unroll
    for (int p = 0; p < 2; p++) {
        const __half* pa = gA + (size_t)p * KTILE;
        const __half* pb = gB + (size_t)(p & 63) * KTILE;
#pragma unroll
        for (int j = 0; j < 4; j++) {
            cp_async16(sA[p] + soff[j], pa + j * 8);
            cp_async16(sB[p] + soff[j], pb + j * 8);
        }
        CP_COMMIT();
    }

    for (int it = 0; it < KITER; ++it) {
        const int s = it & 1;
        if (it + 1 < KITER) CP_WAIT(1); else CP_WAIT(0);
        __syncthreads();

#pragma unroll
        for (int ks = 0; ks < 4; ks++) {
            uint32_t aF[4][4], bF[2][4];
            const uint32_t acol = (uint32_t)(ks * 2 + kc) * 16u;
#pragma unroll
            for (int mt = 0; mt < 4; mt++)
                ldsm_x4(aF[mt], sA[s] + sw128((uint32_t)(arow + mt * 16) * 128u + acol));
            ldsm_x4(bF[0], sB[s] + sw128((uint32_t)(brow)      * 128u + acol));
            ldsm_x4(bF[1], sB[s] + sw128((uint32_t)(brow + 16) * 128u + acol));
#pragma unroll
            for (int mt = 0; mt < 4; mt++)
#pragma unroll
                for (int nt = 0; nt < 4; nt++) {
                    const int gsel = nt >> 1, sub = nt & 1;
                    mma16816(acc[mt][nt], aF[mt], bF[gsel][sub], bF[gsel][sub + 2]);
                }
        }
        __syncthreads();

        if (it + 2 < KITER) {
            const int sn = s;
            const __half* pa = gA + (size_t)(it + 2) * KTILE;
            const __half* pb = gB + (size_t)((it + 2) & 63) * KTILE;
#pragma unroll
            for (int j = 0; j < 4; j++) {
                cp_async16(sA[sn] + soff[j], pa + j * 8);
                cp_async16(sB[sn] + soff[j], pb + j * 8);
            }
            CP_COMMIT();
        }
    }

#pragma unroll
    for (int mt = 0; mt < 4; mt++) {
        const int row0 = m0 + wm * 64 + mt * 16 + (lane >> 2);
#pragma unroll
        for (int nt = 0; nt < 4; nt++) {
            const int col = n0 + wn * 32 + nt * 8 + (lane & 3) * 2;
            float2 lo = { acc[mt][nt][0], acc[mt][nt][1] };
            float2 hi = { acc[mt][nt][2], acc[mt][nt][3] };
            *(float2*)(C + (size_t)row0 * N + col)       = lo;
            *(float2*)(C + (size_t)(row0 + 8) * N + col) = hi;
        }
    }
}

/* -------- RoPE -> fp16 Q/K layouts + V fp16 transpose [g][d][s] ---------- */
__global__ __launch_bounds__(256) void rope_split(const int* __restrict__ positions) {
    const int s = blockIdx.x;
    const float* row = g_qkv + (size_t)s * QKV_N;
    const float pos = (float)positions[s];
    const int tid = threadIdx.x;
    const float LN_THETA_OVER_HALF = 9.210340371976184f / 64.0f;

    for (int idx = tid; idx < NQ * HALF; idx += 256) {
        int h = idx >> 6, j = idx & 63;
        float inv = expf(-(float)j * LN_THETA_OVER_HALF);
        float f = pos * inv;
        float c = cosf(f), sn = sinf(f);
        float x1 = row[h * HD + j];
        float x2 = row[h * HD + HALF + j];
        __half* o = g_qh + ((size_t)h * S_LEN + s) * HD;
        o[j]        = __float2half_rn(x1 * c - x2 * sn);
        o[HALF + j] = __float2half_rn(x2 * c + x1 * sn);
    }
    for (int idx = tid; idx < NKV * HALF; idx += 256) {
        int h = idx >> 6, j = idx & 63;
        float inv = expf(-(float)j * LN_THETA_OVER_HALF);
        float f = pos * inv;
        float c = cosf(f), sn = sinf(f);
        const float* kr = row + NQ * HD;
        float x1 = kr[h * HD + j];
        float x2 = kr[h * HD + HALF + j];
        __half* o = g_kh + ((size_t)h * S_LEN + s) * HD;
        o[j]        = __float2half_rn(x1 * c - x2 * sn);
        o[HALF + j] = __float2half_rn(x2 * c + x1 * sn);
    }
    /* V: fp32 -> fp16, transposed to [g][d][s] */
    for (int idx = tid; idx < NKV * HD; idx += 256) {
        int g = idx >> 7, d = idx & 127;
        float x = row[NQ * HD + NKV * HD + g * HD + d];
        g_vh[((size_t)g * HD + d) * S_LEN + s] = __float2half_rn(x);
    }
}

/* ======== tensor-core flash attention: Br=128, Bc=64, causal, fp16 =======
   K+V double-buffered via cp.async; V pre-converted in g_vh [g][d][s].      */
#define AS_Q    0
#define AS_K0   32768
#define AS_V0   (AS_K0 + 16384)
#define AS_K1   (AS_V0 + 16384)
#define AS_V1   (AS_K1 + 16384)
#define AS_KP   (AS_V1 + 16384)          /* kp[2][64] ints */
#define AS_TOT  (AS_KP + 512)

__global__ __launch_bounds__(256) void attn_mma(const int* __restrict__ positions) {
    extern __shared__ char smc[];
    const uint32_t smb = smem_u32(smc);
    int* kp = (int*)(smc + AS_KP);

    const int h  = blockIdx.y;
    const int qt = 31 - blockIdx.x;
    const int g  = h / GRP;
    const int tid  = threadIdx.x;
    const int lane = tid & 31;
    const int w    = tid >> 5;
    const int kc   = lane >> 4;

    const uint32_t sK[2] = { smb + AS_K0, smb + AS_K1 };
    const uint32_t sV[2] = { smb + AS_V0, smb + AS_V1 };

    /* Q tile (128 x 128 fp16), phys rows = m*2+half */
    const __half* qg = g_qh + ((size_t)h * S_LEN + (size_t)qt * 128) * HD;
    for (int c = tid; c < 2048; c += 256) {
        int s = c >> 4, cc = c & 15;
        uint32_t dst = smb + AS_Q +
            sw128((uint32_t)(s * 2 + (cc >> 3)) * 128u + (uint32_t)(cc & 7) * 16u);
        cp_async16(dst, (const char*)qg + (size_t)c * 16);
    }

    const __half* kgb = g_kh + (size_t)g * S_LEN * HD;
    const __half* vgb = g_vh + (size_t)g * HD * S_LEN;

    /* KV tile loader: stage st <- tile kt */
    const int ntiles = 2 * qt + 2;
#define LOAD_KV(st, kt_)  do {                                                \
        const __half* kg_ = kgb + (size_t)(kt_) * 64 * HD;                    \
        for (int c = tid; c < 1024; c += 256) {                               \
            int s_ = c >> 4, cc_ = c & 15;                                    \
            uint32_t dst_ = sK[st] +                                          \
                sw128((uint32_t)(s_ * 2 + (cc_ >> 3)) * 128u +                \
                      (uint32_t)(cc_ & 7) * 16u);                             \
            cp_async16(dst_, (const char*)kg_ + (size_t)c * 16);              \
        }                                                                     \
        for (int c = tid; c < 1024; c += 256) {                               \
            int d_ = c >> 3, j_ = c & 7;                                      \
            uint32_t dst_ = sV[st] + sw128((uint32_t)d_ * 128u +              \
                                           (uint32_t)j_ * 16u);               \
            cp_async16(dst_, (const char*)(vgb + (size_t)d_ * S_LEN +         \
                                           (size_t)(kt_) * 64) + j_ * 16);    \
        }                                                                     \
        if (tid < 64) kp[(st) * 64 + tid] = positions[(kt_) * 64 + tid];      \
    } while (0)

    LOAD_KV(0, 0);
    CP_COMMIT();   /* group: Q + KV0 */

    const int qr = qt * 128 + w * 16 + (lane >> 2);
    const int qpos0 = positions[qr];
    const int qpos1 = positions[qr + 8];

    float m_i[2] = { -1e30f, -1e30f };
    float l_i[2] = { 0.0f, 0.0f };
    float acc[16][4];
#pragma unroll
    for (int t = 0; t < 16; t++)
#pragma unroll
        for (int q = 0; q < 4; q++) acc[t][q] = 0.0f;

    for (int kt = 0; kt < ntiles; kt++) {
        const int st = kt & 1;
        CP_WAIT(0);          /* stage st data landed (overlapped w/ prev compute) */
        __syncthreads();     /* visible to all; stage st^1 free (readers done)    */

        if (kt + 1 < ntiles) {
            LOAD_KV(st ^ 1, kt + 1);
            CP_COMMIT();
        }

        /* ---- scores: S = Q K^T (16 x 64 per warp) ---- */
        float sc[8][4];
#pragma unroll
        for (int j = 0; j < 8; j++)
#pragma unroll
            for (int q = 0; q < 4; q++) sc[j][q] = 0.0f;

#pragma unroll
        for (int ks = 0; ks < 8; ks++) {
            const int cc = 2 * ks + kc;
            uint32_t aF[4];
            {
                int m = w * 16 + (lane & 15);
                ldsm_x4(aF, smb + AS_Q +
                    sw128((uint32_t)(m * 2 + (cc >> 3)) * 128u + (uint32_t)(cc & 7) * 16u));
            }
#pragma unroll
            for (int grp = 0; grp < 4; grp++) {
                uint32_t bF[4];
                int kv = grp * 16 + (lane & 15);
                ldsm_x4(bF, sK[st] +
                    sw128((uint32_t)(kv * 2 + (cc >> 3)) * 128u + (uint32_t)(cc & 7) * 16u));
                mma16816(sc[grp * 2 + 0], aF, bF[0], bF[2]);
                mma16816(sc[grp * 2 + 1], aF, bF[1], bF[3]);
            }
        }

        /* ---- scale + causal mask ---- */
#pragma unroll
        for (int j = 0; j < 8; j++) {
            int kcol = j * 8 + 2 * (lane & 3);
            int kp0 = kp[st * 64 + kcol], kp1 = kp[st * 64 + kcol + 1];
            float s0 = sc[j][0] * ATT_SCALE, s1 = sc[j][1] * ATT_SCALE;
            float s2 = sc[j][2] * ATT_SCALE, s3 = sc[j][3] * ATT_SCALE;
            sc[j][0] = (qpos0 >= kp0) ? s0 : -1e30f;
            sc[j][1] = (qpos0 >= kp1) ? s1 : -1e30f;
            sc[j][2] = (qpos1 >= kp0) ? s2 : -1e30f;
            sc[j][3] = (qpos1 >= kp1) ? s3 : -1e30f;
        }

        /* ---- online softmax ---- */
        float mt0 = -1e30f, mt1 = -1e30f;
#pragma unroll
        for (int j = 0; j < 8; j++) {
            mt0 = fmaxf(mt0, fmaxf(sc[j][0], sc[j][1]));
            mt1 = fmaxf(mt1, fmaxf(sc[j][2], sc[j][3]));
        }
        mt0 = fmaxf(mt0, __shfl_xor_sync(0xffffffffu, mt0, 1));
        mt0 = fmaxf(mt0, __shfl_xor_sync(0xffffffffu, mt0, 2));
        mt1 = fmaxf(mt1, __shfl_xor_sync(0xffffffffu, mt1, 1));
        mt1 = fmaxf(mt1, __shfl_xor_sync(0xffffffffu, mt1, 2));

        float mn0 = fmaxf(m_i[0], mt0), mn1 = fmaxf(m_i[1], mt1);
        float al0 = __expf(m_i[0] - mn0), al1 = __expf(m_i[1] - mn1);
        m_i[0] = mn0; m_i[1] = mn1;

        float rs0 = 0.0f, rs1 = 0.0f;
#pragma unroll
        for (int j = 0; j < 8; j++) {
            sc[j][0] = __expf(sc[j][0] - mn0);
            sc[j][1] = __expf(sc[j][1] - mn0);
            sc[j][2] = __expf(sc[j][2] - mn1);
            sc[j][3] = __expf(sc[j][3] - mn1);
            rs0 += sc[j][0] + sc[j][1];
            rs1 += sc[j][2] + sc[j][3];
        }
        rs0 += __shfl_xor_sync(0xffffffffu, rs0, 1);
        rs0 += __shfl_xor_sync(0xffffffffu, rs0, 2);
        rs1 += __shfl_xor_sync(0xffffffffu, rs1, 1);
        rs1 += __shfl_xor_sync(0xffffffffu, rs1, 2);
        l_i[0] = l_i[0] * al0 + rs0;
        l_i[1] = l_i[1] * al1 + rs1;

#pragma unroll
        for (int t = 0; t < 16; t++) {
            acc[t][0] *= al0; acc[t][1] *= al0;
            acc[t][2] *= al1; acc[t][3] *= al1;
        }

        /* ---- PV: acc += (Phi + Plo) * Vh  (exact P x Vh) ---- */
#pragma unroll
        for (int ks = 0; ks < 4; ks++) {
            const int j0 = 2 * ks, j1 = 2 * ks + 1;
            uint32_t ahi[4], alo[4];
            ahi[0] = pack_h2(sc[j0][0], sc[j0][1]);
            ahi[1] = pack_h2(sc[j0][2], sc[j0][3]);
            ahi[2] = pack_h2(sc[j1][0], sc[j1][1]);
            ahi[3] = pack_h2(sc[j1][2], sc[j1][3]);
            {
                __half2* hp;
                hp = (__half2*)&ahi[0];
                alo[0] = pack_h2(sc[j0][0] - __half2float(hp->x),
                                 sc[j0][1] - __half2float(hp->y));
                hp = (__half2*)&ahi[1];
                alo[1] = pack_h2(sc[j0][2] - __half2float(hp->x),
                                 sc[j0][3] - __half2float(hp->y));
                hp = (__half2*)&ahi[2];
                alo[2] = pack_h2(sc[j1][0] - __half2float(hp->x),
                                 sc[j1][1] - __half2float(hp->y));
                hp = (__half2*)&ahi[3];
                alo[3] = pack_h2(sc[j1][2] - __half2float(hp->x),
                                 sc[j1][3] - __half2float(hp->y));
            }
            const uint32_t ccol = (uint32_t)(2 * ks + kc) * 16u;
#pragma unroll
            for (int grp = 0; grp < 8; grp++) {
                uint32_t vh[4];
                uint32_t roff = sw128((uint32_t)(grp * 16 + (lane & 15)) * 128u + ccol);
                ldsm_x4(vh, sV[st] + roff);
                const int t0 = grp * 2, t1 = grp * 2 + 1;
                mma16816(acc[t0], ahi, vh[0], vh[2]);
                mma16816(acc[t1], ahi, vh[1], vh[3]);
                mma16816(acc[t0], alo, vh[0], vh[2]);
                mma16816(acc[t1], alo, vh[1], vh[3]);
            }
        }
        __syncthreads();  /* all reads of stage st done before its refill at kt+2 */
    }

    /* ---- epilogue: normalize + write split-fp16 [hi|lo] into g_Ah ------- */
    float inv0 = 1.0f / l_i[0];
    float inv1 = 1.0f / l_i[1];
    const size_t base0 = (size_t)qr * KP;
    const size_t base1 = (size_t)(qr + 8) * KP;
#pragma unroll
    for (int t = 0; t < 16; t++) {
        int col = h * HD + t * 8 + (lane & 3) * 2;
        float o00 = acc[t][0] * inv0, o01 = acc[t][1] * inv0;
        float o10 = acc[t][2] * inv1, o11 = acc[t][3] * inv1;

        uint32_t h0 = pack_h2(o00, o01);
        __half2 hh0 = *(__half2*)&h0;
        uint32_t l0 = pack_h2(o00 - __half2float(hh0.x),
                              o01 - __half2float(hh0.y));
        uint32_t h1 = pack_h2(o10, o11);
        __half2 hh1 = *(__half2*)&h1;
        uint32_t l1 = pack_h2(o10 - __half2float(hh1.x),
                              o11 - __half2float(hh1.y));

        *(uint32_t*)(g_Ah + base0 + col)        = h0;
        *(uint32_t*)(g_Ah + base0 + HID + col)  = l0;
        *(uint32_t*)(g_Ah + base1 + col)        = h1;
        *(uint32_t*)(g_Ah + base1 + HID + col)  = l1;
    }
}

/* ------------------------------- launch ---------------------------------- */
extern "C" void kernel_launch(void* const* d_in, const int* in_sizes, int n_in,
                              void* d_out, int out_size) {
    const int*   positions = (const int*)  d_in[0];
    const float* hidden    = (const float*)d_in[1];
    const float* w_qkv     = (const float*)d_in[2];
    const float* w_o       = (const float*)d_in[3];
    float*       out       = (float*)d_out;
    (void)in_sizes; (void)n_in; (void)out_size;

    void *p_qkv = nullptr, *p_ah = nullptr, *p_wq = nullptr, *p_wo = nullptr;
    cudaGetSymbolAddress(&p_qkv, g_qkv);
    cudaGetSymbolAddress(&p_ah,  g_Ah);
    cudaGetSymbolAddress(&p_wq,  g_Wq);
    cudaGetSymbolAddress(&p_wo,  g_Wo);

    const int gemm_smem = 4 * TILE_BYTES;   /* 64 KB */
    cudaFuncSetAttribute(gemm_mma, cudaFuncAttributeMaxDynamicSharedMemorySize,
                         gemm_smem);
    cudaFuncSetAttribute(attn_mma, cudaFuncAttributeMaxDynamicSharedMemorySize,
                         AS_TOT);

    /* 0) fp16 conversions */
    split_rows<<<(S_LEN * HID) / 256, 256>>>(hidden, (__half*)p_ah);
    conv_wt<<<dim3(HID / 32, QKV_N / 32), dim3(32, 8)>>>(w_qkv, (__half*)p_wq, QKV_N);
    conv_wt<<<dim3(HID / 32, HID / 32), dim3(32, 8)>>>(w_o, (__half*)p_wo, HID);

    /* 1) QKV projection (tensor cores, split-fp16 2-term) */
    gemm_mma<<<dim3(S_LEN / 128, QKV_N / 128), 256, gemm_smem>>>(
        (const __half*)p_ah, (const __half*)p_wq, (float*)p_qkv, QKV_N);

    /* 2) RoPE -> fp16 Q/K + V fp16 transpose */
    rope_split<<<S_LEN, 256>>>(positions);

    /* 3) tensor-core flash attention (double-buffered K/V) */
    attn_mma<<<dim3(32, NQ), 256, AS_TOT>>>(positions);

    /* 4) output projection (tensor cores) */
    gemm_mma<<<dim3(S_LEN / 128, HID / 128), 256, gemm_smem>>>(
        (const __half*)p_ah, (const __half*)p_wo, out, HID);
}

// round 15
// speedup vs baseline: 1.6487x; 1.1799x over previous
#include <cuda_runtime.h>
#include <cuda_fp16.h>
#include <cstdint>
#include <cstddef>

#define S_LEN 4096
#define HID   4096
#define NQ    32
#define NKV   8
#define HD    128
#define HALF  64
#define GRP   4
#define QKV_N (NQ*HD + 2*NKV*HD)   /* 6144 */
#define ATT_SCALE 0.08838834764831845f
#define KP    (2*HID)              /* 8192: hidden split [hi | lo] fp16 */
#define KW    HID                  /* 4096: B = [hi] fp16 */
#define KTILE 64

/* ---------------- scratch (device globals: allocation-free) -------------- */
__device__ float  g_qkv[(size_t)S_LEN * QKV_N];
__device__ __half g_qh [(size_t)NQ  * S_LEN * HD];   /* roped Q fp16 [h][s][d] */
__device__ __half g_kh [(size_t)NKV * S_LEN * HD];   /* roped K fp16 [g][s][d] */
__device__ __half g_vh [(size_t)NKV * HD * S_LEN];   /* V fp16 [g][d][s]       */
__device__ __half g_Xh [(size_t)S_LEN * KP];         /* split hidden [hi|lo]   */
__device__ __half g_Ah [(size_t)S_LEN * HID];        /* attention out, hi only */
__device__ __half g_Wq [(size_t)QKV_N * KW];
__device__ __half g_Wo [(size_t)HID   * KW];

/* ======================= small asm helpers =============================== */
__device__ __forceinline__ uint32_t smem_u32(const void* p) {
    uint32_t a;
    asm("{ .reg .u64 t; cvta.to.shared.u64 t, %1; cvt.u32.u64 %0, t; }"
        : "=r"(a) : "l"(p));
    return a;
}
__device__ __forceinline__ uint32_t sw128(uint32_t off) {   /* Swizzle<3,4,3> */
    return off ^ ((off >> 3) & 0x70);
}
__device__ __forceinline__ void cp_async16(uint32_t saddr, const void* gaddr) {
    asm volatile("cp.async.cg.shared.global [%0], [%1], 16;"
                 :: "r"(saddr), "l"(gaddr));
}
#define CP_COMMIT() asm volatile("cp.async.commit_group;" ::: "memory")
#define CP_WAIT(n)  asm volatile("cp.async.wait_group %0;" :: "n"(n) : "memory")

__device__ __forceinline__ void ldsm_x4(uint32_t* f, uint32_t addr) {
    asm volatile("ldmatrix.sync.aligned.m8n8.x4.shared.b16 {%0,%1,%2,%3}, [%4];"
                 : "=r"(f[0]), "=r"(f[1]), "=r"(f[2]), "=r"(f[3]) : "r"(addr));
}
__device__ __forceinline__ void mma16816(float* d, const uint32_t* a,
                                         uint32_t b0, uint32_t b1) {
    asm volatile("mma.sync.aligned.m16n8k16.row.col.f32.f16.f16.f32 "
                 "{%0,%1,%2,%3}, {%4,%5,%6,%7}, {%8,%9}, {%0,%1,%2,%3};"
                 : "+f"(d[0]), "+f"(d[1]), "+f"(d[2]), "+f"(d[3])
                 : "r"(a[0]), "r"(a[1]), "r"(a[2]), "r"(a[3]), "r"(b0), "r"(b1));
}
__device__ __forceinline__ uint32_t pack_h2(float x, float y) {
    __half2 h = __floats2half2_rn(x, y);
    return *(uint32_t*)&h;
}

/* ================= fp16 conversion kernels =============================== */
__global__ __launch_bounds__(256) void split_rows(const float* __restrict__ src,
                                                  __half* __restrict__ dst) {
    size_t idx = (size_t)blockIdx.x * 256 + threadIdx.x;
    int r = (int)(idx >> 12), k = (int)(idx & 4095);
    float x = src[idx];
    __half hi = __float2half_rn(x);
    __half lo = __float2half_rn(x - __half2float(hi));
    size_t base = (size_t)r * KP + k;
    dst[base]       = hi;
    dst[base + HID] = lo;
}
__global__ __launch_bounds__(256) void conv_wt(const float* __restrict__ src,
                                               __half* __restrict__ dst, int N) {
    __shared__ float t[32][33];
    int kb = blockIdx.x * 32, nb = blockIdx.y * 32;
    int tx = threadIdx.x, ty = threadIdx.y;
#pragma unroll
    for (int i = 0; i < 32; i += 8)
        t[ty + i][tx] = src[(size_t)(kb + ty + i) * N + nb + tx];
    __syncthreads();
#pragma unroll
    for (int i = 0; i < 32; i += 8) {
        int n = nb + ty + i, k = kb + tx;
        dst[(size_t)n * KW + k] = __float2half_rn(t[tx][ty + i]);
    }
}

/* ========== mma.sync fp16 GEMM (R11-validated shape, 256 thr) ============
   A: [M, astride] fp16 (kiter K-tiles consumed);  B: [N, KW], tile (it&63) */
#define TILE_BYTES 16384

__global__ __launch_bounds__(256) void gemm_mma(const __half* __restrict__ A,
                                                const __half* __restrict__ B,
                                                float* __restrict__ C, int N,
                                                int astride, int kiter) {
    extern __shared__ char smc[];
    const uint32_t smb = smem_u32(smc);
    const int tid  = threadIdx.x;
    const int lane = tid & 31;
    const int wid  = tid >> 5;
    const int wm   = wid & 1;
    const int wn   = wid >> 1;
    const int m0   = blockIdx.x * 128;
    const int n0   = blockIdx.y * 128;

    const uint32_t sA[2] = { smb,              smb + 2*TILE_BYTES };
    const uint32_t sB[2] = { smb + TILE_BYTES, smb + 3*TILE_BYTES };

    const int r    = tid >> 1;
    const int halfc= tid & 1;
    const __half* gA = A + (size_t)(m0 + r) * astride + halfc * 32;
    const __half* gB = B + (size_t)(n0 + r) * KW + halfc * 32;
    const uint32_t soff[4] = {
        sw128((uint32_t)r * 128u + (uint32_t)(halfc * 4 + 0) * 16u),
        sw128((uint32_t)r * 128u + (uint32_t)(halfc * 4 + 1) * 16u),
        sw128((uint32_t)r * 128u + (uint32_t)(halfc * 4 + 2) * 16u),
        sw128((uint32_t)r * 128u + (uint32_t)(halfc * 4 + 3) * 16u) };

    float acc[4][4][4];
#pragma unroll
    for (int i = 0; i < 4; i++)
#pragma unroll
        for (int j = 0; j < 4; j++)
#pragma unroll
            for (int q = 0; q < 4; q++) acc[i][j][q] = 0.0f;

    const int arow = wm * 64 + (lane & 15);
    const int brow = wn * 32 + (lane & 15);
    const int kc   = lane >> 4;

#pragma unroll
    for (int p = 0; p < 2; p++) {
        const __half* pa = gA + (size_t)p * KTILE;
        const __half* pb = gB + (size_t)(p & 63) * KTILE;
#pragma unroll
        for (int j = 0; j < 4; j++) {
            cp_async16(sA[p] + soff[j], pa + j * 8);
            cp_async16(sB[p] + soff[j], pb + j * 8);
        }
        CP_COMMIT();
    }

    for (int it = 0; it < kiter; ++it) {
        const int s = it & 1;
        if (it + 1 < kiter) CP_WAIT(1); else CP_WAIT(0);
        __syncthreads();

#pragma unroll
        for (int ks = 0; ks < 4; ks++) {
            uint32_t aF[4][4], bF[2][4];
            const uint32_t acol = (uint32_t)(ks * 2 + kc) * 16u;
#pragma unroll
            for (int mt = 0; mt < 4; mt++)
                ldsm_x4(aF[mt], sA[s] + sw128((uint32_t)(arow + mt * 16) * 128u + acol));
            ldsm_x4(bF[0], sB[s] + sw128((uint32_t)(brow)      * 128u + acol));
            ldsm_x4(bF[1], sB[s] + sw128((uint32_t)(brow + 16) * 128u + acol));
#pragma unroll
            for (int mt = 0; mt < 4; mt++)
#pragma unroll
                for (int nt = 0; nt < 4; nt++) {
                    const int gsel = nt >> 1, sub = nt & 1;
                    mma16816(acc[mt][nt], aF[mt], bF[gsel][sub], bF[gsel][sub + 2]);
                }
        }
        __syncthreads();

        if (it + 2 < kiter) {
            const int sn = s;
            const __half* pa = gA + (size_t)(it + 2) * KTILE;
            const __half* pb = gB + (size_t)((it + 2) & 63) * KTILE;
#pragma unroll
            for (int j = 0; j < 4; j++) {
                cp_async16(sA[sn] + soff[j], pa + j * 8);
                cp_async16(sB[sn] + soff[j], pb + j * 8);
            }
            CP_COMMIT();
        }
    }

#pragma unroll
    for (int mt = 0; mt < 4; mt++) {
        const int row0 = m0 + wm * 64 + mt * 16 + (lane >> 2);
#pragma unroll
        for (int nt = 0; nt < 4; nt++) {
            const int col = n0 + wn * 32 + nt * 8 + (lane & 3) * 2;
            float2 lo = { acc[mt][nt][0], acc[mt][nt][1] };
            float2 hi = { acc[mt][nt][2], acc[mt][nt][3] };
            *(float2*)(C + (size_t)row0 * N + col)       = lo;
            *(float2*)(C + (size_t)(row0 + 8) * N + col) = hi;
        }
    }
}

/* -------- RoPE -> fp16 Q/K layouts + V fp16 transpose [g][d][s] ---------- */
__global__ __launch_bounds__(256) void rope_split(const int* __restrict__ positions) {
    const int s = blockIdx.x;
    const float* row = g_qkv + (size_t)s * QKV_N;
    const float pos = (float)positions[s];
    const int tid = threadIdx.x;
    const float LN_THETA_OVER_HALF = 9.210340371976184f / 64.0f;

    for (int idx = tid; idx < NQ * HALF; idx += 256) {
        int h = idx >> 6, j = idx & 63;
        float inv = expf(-(float)j * LN_THETA_OVER_HALF);
        float f = pos * inv;
        float c = cosf(f), sn = sinf(f);
        float x1 = row[h * HD + j];
        float x2 = row[h * HD + HALF + j];
        __half* o = g_qh + ((size_t)h * S_LEN + s) * HD;
        o[j]        = __float2half_rn(x1 * c - x2 * sn);
        o[HALF + j] = __float2half_rn(x2 * c + x1 * sn);
    }
    for (int idx = tid; idx < NKV * HALF; idx += 256) {
        int h = idx >> 6, j = idx & 63;
        float inv = expf(-(float)j * LN_THETA_OVER_HALF);
        float f = pos * inv;
        float c = cosf(f), sn = sinf(f);
        const float* kr = row + NQ * HD;
        float x1 = kr[h * HD + j];
        float x2 = kr[h * HD + HALF + j];
        __half* o = g_kh + ((size_t)h * S_LEN + s) * HD;
        o[j]        = __float2half_rn(x1 * c - x2 * sn);
        o[HALF + j] = __float2half_rn(x2 * c + x1 * sn);
    }
    for (int idx = tid; idx < NKV * HD; idx += 256) {
        int g = idx >> 7, d = idx & 127;
        float x = row[NQ * HD + NKV * HD + g * HD + d];
        g_vh[((size_t)g * HD + d) * S_LEN + s] = __float2half_rn(x);
    }
}

/* ======== tensor-core flash attention: Br=128, Bc=64, causal, fp16 =======
   K+V double-buffered; epilogue writes hi-only fp16 into g_Ah.              */
#define AS_Q    0
#define AS_K0   32768
#define AS_V0   (AS_K0 + 16384)
#define AS_K1   (AS_V0 + 16384)
#define AS_V1   (AS_K1 + 16384)
#define AS_KP   (AS_V1 + 16384)
#define AS_TOT  (AS_KP + 512)

__global__ __launch_bounds__(256) void attn_mma(const int* __restrict__ positions) {
    extern __shared__ char smc[];
    const uint32_t smb = smem_u32(smc);
    int* kp = (int*)(smc + AS_KP);

    const int h  = blockIdx.y;
    const int qt = 31 - blockIdx.x;
    const int g  = h / GRP;
    const int tid  = threadIdx.x;
    const int lane = tid & 31;
    const int w    = tid >> 5;
    const int kc   = lane >> 4;

    const uint32_t sK[2] = { smb + AS_K0, smb + AS_K1 };
    const uint32_t sV[2] = { smb + AS_V0, smb + AS_V1 };

    const __half* qg = g_qh + ((size_t)h * S_LEN + (size_t)qt * 128) * HD;
    for (int c = tid; c < 2048; c += 256) {
        int s = c >> 4, cc = c & 15;
        uint32_t dst = smb + AS_Q +
            sw128((uint32_t)(s * 2 + (cc >> 3)) * 128u + (uint32_t)(cc & 7) * 16u);
        cp_async16(dst, (const char*)qg + (size_t)c * 16);
    }

    const __half* kgb = g_kh + (size_t)g * S_LEN * HD;
    const __half* vgb = g_vh + (size_t)g * HD * S_LEN;

    const int ntiles = 2 * qt + 2;
#define LOAD_KV(st, kt_)  do {                                                \
        const __half* kg_ = kgb + (size_t)(kt_) * 64 * HD;                    \
        for (int c = tid; c < 1024; c += 256) {                               \
            int s_ = c >> 4, cc_ = c & 15;                                    \
            uint32_t dst_ = sK[st] +                                          \
                sw128((uint32_t)(s_ * 2 + (cc_ >> 3)) * 128u +                \
                      (uint32_t)(cc_ & 7) * 16u);                             \
            cp_async16(dst_, (const char*)kg_ + (size_t)c * 16);              \
        }                                                                     \
        for (int c = tid; c < 1024; c += 256) {                               \
            int d_ = c >> 3, j_ = c & 7;                                      \
            uint32_t dst_ = sV[st] + sw128((uint32_t)d_ * 128u +              \
                                           (uint32_t)j_ * 16u);               \
            cp_async16(dst_, (const char*)(vgb + (size_t)d_ * S_LEN +         \
                                           (size_t)(kt_) * 64) + j_ * 16);    \
        }                                                                     \
        if (tid < 64) kp[(st) * 64 + tid] = positions[(kt_) * 64 + tid];      \
    } while (0)

    LOAD_KV(0, 0);
    CP_COMMIT();

    const int qr = qt * 128 + w * 16 + (lane >> 2);
    const int qpos0 = positions[qr];
    const int qpos1 = positions[qr + 8];

    float m_i[2] = { -1e30f, -1e30f };
    float l_i[2] = { 0.0f, 0.0f };
    float acc[16][4];
#pragma unroll
    for (int t = 0; t < 16; t++)
#pragma unroll
        for (int q = 0; q < 4; q++) acc[t][q] = 0.0f;

    for (int kt = 0; kt < ntiles; kt++) {
        const int st = kt & 1;
        CP_WAIT(0);
        __syncthreads();

        if (kt + 1 < ntiles) {
            LOAD_KV(st ^ 1, kt + 1);
            CP_COMMIT();
        }

        float sc[8][4];
#pragma unroll
        for (int j = 0; j < 8; j++)
#pragma unroll
            for (int q = 0; q < 4; q++) sc[j][q] = 0.0f;

#pragma unroll
        for (int ks = 0; ks < 8; ks++) {
            const int cc = 2 * ks + kc;
            uint32_t aF[4];
            {
                int m = w * 16 + (lane & 15);
                ldsm_x4(aF, smb + AS_Q +
                    sw128((uint32_t)(m * 2 + (cc >> 3)) * 128u + (uint32_t)(cc & 7) * 16u));
            }
#pragma unroll
            for (int grp = 0; grp < 4; grp++) {
                uint32_t bF[4];
                int kv = grp * 16 + (lane & 15);
                ldsm_x4(bF, sK[st] +
                    sw128((uint32_t)(kv * 2 + (cc >> 3)) * 128u + (uint32_t)(cc & 7) * 16u));
                mma16816(sc[grp * 2 + 0], aF, bF[0], bF[2]);
                mma16816(sc[grp * 2 + 1], aF, bF[1], bF[3]);
            }
        }

#pragma unroll
        for (int j = 0; j < 8; j++) {
            int kcol = j * 8 + 2 * (lane & 3);
            int kp0 = kp[st * 64 + kcol], kp1 = kp[st * 64 + kcol + 1];
            float s0 = sc[j][0] * ATT_SCALE, s1 = sc[j][1] * ATT_SCALE;
            float s2 = sc[j][2] * ATT_SCALE, s3 = sc[j][3] * ATT_SCALE;
            sc[j][0] = (qpos0 >= kp0) ? s0 : -1e30f;
            sc[j][1] = (qpos0 >= kp1) ? s1 : -1e30f;
            sc[j][2] = (qpos1 >= kp0) ? s2 : -1e30f;
            sc[j][3] = (qpos1 >= kp1) ? s3 : -1e30f;
        }

        float mt0 = -1e30f, mt1 = -1e30f;
#pragma unroll
        for (int j = 0; j < 8; j++) {
            mt0 = fmaxf(mt0, fmaxf(sc[j][0], sc[j][1]));
            mt1 = fmaxf(mt1, fmaxf(sc[j][2], sc[j][3]));
        }
        mt0 = fmaxf(mt0, __shfl_xor_sync(0xffffffffu, mt0, 1));
        mt0 = fmaxf(mt0, __shfl_xor_sync(0xffffffffu, mt0, 2));
        mt1 = fmaxf(mt1, __shfl_xor_sync(0xffffffffu, mt1, 1));
        mt1 = fmaxf(mt1, __shfl_xor_sync(0xffffffffu, mt1, 2));

        float mn0 = fmaxf(m_i[0], mt0), mn1 = fmaxf(m_i[1], mt1);
        float al0 = __expf(m_i[0] - mn0), al1 = __expf(m_i[1] - mn1);
        m_i[0] = mn0; m_i[1] = mn1;

        float rs0 = 0.0f, rs1 = 0.0f;
#pragma unroll
        for (int j = 0; j < 8; j++) {
            sc[j][0] = __expf(sc[j][0] - mn0);
            sc[j][1] = __expf(sc[j][1] - mn0);
            sc[j][2] = __expf(sc[j][2] - mn1);
            sc[j][3] = __expf(sc[j][3] - mn1);
            rs0 += sc[j][0] + sc[j][1];
            rs1 += sc[j][2] + sc[j][3];
        }
        rs0 += __shfl_xor_sync(0xffffffffu, rs0, 1);
        rs0 += __shfl_xor_sync(0xffffffffu, rs0, 2);
        rs1 += __shfl_xor_sync(0xffffffffu, rs1, 1);
        rs1 += __shfl_xor_sync(0xffffffffu, rs1, 2);
        l_i[0] = l_i[0] * al0 + rs0;
        l_i[1] = l_i[1] * al1 + rs1;

#pragma unroll
        for (int t = 0; t < 16; t++) {
            acc[t][0] *= al0; acc[t][1] *= al0;
            acc[t][2] *= al1; acc[t][3] *= al1;
        }

#pragma unroll
        for (int ks = 0; ks < 4; ks++) {
            const int j0 = 2 * ks, j1 = 2 * ks + 1;
            uint32_t ahi[4], alo[4];
            ahi[0] = pack_h2(sc[j0][0], sc[j0][1]);
            ahi[1] = pack_h2(sc[j0][2], sc[j0][3]);
            ahi[2] = pack_h2(sc[j1][0], sc[j1][1]);
            ahi[3] = pack_h2(sc[j1][2], sc[j1][3]);
            {
                __half2* hp;
                hp = (__half2*)&ahi[0];
                alo[0] = pack_h2(sc[j0][0] - __half2float(hp->x),
                                 sc[j0][1] - __half2float(hp->y));
                hp = (__half2*)&ahi[1];
                alo[1] = pack_h2(sc[j0][2] - __half2float(hp->x),
                                 sc[j0][3] - __half2float(hp->y));
                hp = (__half2*)&ahi[2];
                alo[2] = pack_h2(sc[j1][0] - __half2float(hp->x),
                                 sc[j1][1] - __half2float(hp->y));
                hp = (__half2*)&ahi[3];
                alo[3] = pack_h2(sc[j1][2] - __half2float(hp->x),
                                 sc[j1][3] - __half2float(hp->y));
            }
            const uint32_t ccol = (uint32_t)(2 * ks + kc) * 16u;
#pragma unroll
            for (int grp = 0; grp < 8; grp++) {
                uint32_t vh[4];
                uint32_t roff = sw128((uint32_t)(grp * 16 + (lane & 15)) * 128u + ccol);
                ldsm_x4(vh, sV[st] + roff);
                const int t0 = grp * 2, t1 = grp * 2 + 1;
                mma16816(acc[t0], ahi, vh[0], vh[2]);
                mma16816(acc[t1], ahi, vh[1], vh[3]);
                mma16816(acc[t0], alo, vh[0], vh[2]);
                mma16816(acc[t1], alo, vh[1], vh[3]);
            }
        }
        __syncthreads();
    }

    /* ---- epilogue: normalize + write hi-only fp16 into g_Ah ------------- */
    float inv0 = 1.0f / l_i[0];
    float inv1 = 1.0f / l_i[1];
    const size_t base0 = (size_t)qr * HID;
    const size_t base1 = (size_t)(qr + 8) * HID;
#pragma unroll
    for (int t = 0; t < 16; t++) {
        int col = h * HD + t * 8 + (lane & 3) * 2;
        *(uint32_t*)(g_Ah + base0 + col) =
            pack_h2(acc[t][0] * inv0, acc[t][1] * inv0);
        *(uint32_t*)(g_Ah + base1 + col) =
            pack_h2(acc[t][2] * inv1, acc[t][3] * inv1);
    }
}

/* ------------------------------- launch ---------------------------------- */
extern "C" void kernel_launch(void* const* d_in, const int* in_sizes, int n_in,
                              void* d_out, int out_size) {
    const int*   positions = (const int*)  d_in[0];
    const float* hidden    = (const float*)d_in[1];
    const float* w_qkv     = (const float*)d_in[2];
    const float* w_o       = (const float*)d_in[3];
    float*       out       = (float*)d_out;
    (void)in_sizes; (void)n_in; (void)out_size;

    void *p_qkv = nullptr, *p_xh = nullptr, *p_ah = nullptr,
         *p_wq = nullptr, *p_wo = nullptr;
    cudaGetSymbolAddress(&p_qkv, g_qkv);
    cudaGetSymbolAddress(&p_xh,  g_Xh);
    cudaGetSymbolAddress(&p_ah,  g_Ah);
    cudaGetSymbolAddress(&p_wq,  g_Wq);
    cudaGetSymbolAddress(&p_wo,  g_Wo);

    const int gemm_smem = 4 * TILE_BYTES;   /* 64 KB */
    cudaFuncSetAttribute(gemm_mma, cudaFuncAttributeMaxDynamicSharedMemorySize,
                         gemm_smem);
    cudaFuncSetAttribute(attn_mma, cudaFuncAttributeMaxDynamicSharedMemorySize,
                         AS_TOT);

    /* 0) fp16 conversions */
    split_rows<<<(S_LEN * HID) / 256, 256>>>(hidden, (__half*)p_xh);
    conv_wt<<<dim3(HID / 32, QKV_N / 32), dim3(32, 8)>>>(w_qkv, (__half*)p_wq, QKV_N);
    conv_wt<<<dim3(HID / 32, HID / 32), dim3(32, 8)>>>(w_o, (__half*)p_wo, HID);

    /* 1) QKV projection: 2-term split-fp16 (K=8192, B cycled) */
    gemm_mma<<<dim3(S_LEN / 128, QKV_N / 128), 256, gemm_smem>>>(
        (const __half*)p_xh, (const __half*)p_wq, (float*)p_qkv, QKV_N, KP, 128);

    /* 2) RoPE -> fp16 Q/K + V fp16 transpose */
    rope_split<<<S_LEN, 256>>>(positions);

    /* 3) tensor-core flash attention (double-buffered K/V) */
    attn_mma<<<dim3(32, NQ), 256, AS_TOT>>>(positions);

    /* 4) output projection: 1-term fp16 (K=4096) */
    gemm_mma<<<dim3(S_LEN / 128, HID / 128), 256, gemm_smem>>>(
        (const __half*)p_ah, (const __half*)p_wo, out, HID, HID, 64);
}

// round 16
// speedup vs baseline: 2.1574x; 1.3086x over previous
#include <cuda_runtime.h>
#include <cuda_fp16.h>
#include <cstdint>
#include <cstddef>

#define S_LEN 4096
#define HID   4096
#define NQ    32
#define NKV   8
#define HD    128
#define HALF  64
#define GRP   4
#define QKV_N (NQ*HD + 2*NKV*HD)   /* 6144 */
#define ATT_SCALE 0.08838834764831845f
#define KW    HID                  /* 4096 */
#define KTILE 64
#define KITER (KW/KTILE)           /* 64 */

/* ---------------- scratch (device globals: allocation-free) -------------- */
__device__ float  g_qkv[(size_t)S_LEN * QKV_N];
__device__ __half g_qh [(size_t)NQ  * S_LEN * HD];   /* roped Q fp16 [h][s][d] */
__device__ __half g_kh [(size_t)NKV * S_LEN * HD];   /* roped K fp16 [g][s][d] */
__device__ __half g_vh [(size_t)NKV * HD * S_LEN];   /* V fp16 [g][d][s]       */
__device__ __half g_Xh [(size_t)S_LEN * HID];        /* hidden fp16 (hi)       */
__device__ __half g_Ah [(size_t)S_LEN * HID];        /* attention out fp16     */
__device__ __half g_Wq [(size_t)QKV_N * KW];
__device__ __half g_Wo [(size_t)HID   * KW];

/* ======================= small asm helpers =============================== */
__device__ __forceinline__ uint32_t smem_u32(const void* p) {
    uint32_t a;
    asm("{ .reg .u64 t; cvta.to.shared.u64 t, %1; cvt.u32.u64 %0, t; }"
        : "=r"(a) : "l"(p));
    return a;
}
__device__ __forceinline__ uint32_t sw128(uint32_t off) {   /* Swizzle<3,4,3> */
    return off ^ ((off >> 3) & 0x70);
}
__device__ __forceinline__ void cp_async16(uint32_t saddr, const void* gaddr) {
    asm volatile("cp.async.cg.shared.global [%0], [%1], 16;"
                 :: "r"(saddr), "l"(gaddr));
}
#define CP_COMMIT() asm volatile("cp.async.commit_group;" ::: "memory")
#define CP_WAIT(n)  asm volatile("cp.async.wait_group %0;" :: "n"(n) : "memory")

__device__ __forceinline__ void ldsm_x4(uint32_t* f, uint32_t addr) {
    asm volatile("ldmatrix.sync.aligned.m8n8.x4.shared.b16 {%0,%1,%2,%3}, [%4];"
                 : "=r"(f[0]), "=r"(f[1]), "=r"(f[2]), "=r"(f[3]) : "r"(addr));
}
__device__ __forceinline__ void mma16816(float* d, const uint32_t* a,
                                         uint32_t b0, uint32_t b1) {
    asm volatile("mma.sync.aligned.m16n8k16.row.col.f32.f16.f16.f32 "
                 "{%0,%1,%2,%3}, {%4,%5,%6,%7}, {%8,%9}, {%0,%1,%2,%3};"
                 : "+f"(d[0]), "+f"(d[1]), "+f"(d[2]), "+f"(d[3])
                 : "r"(a[0]), "r"(a[1]), "r"(a[2]), "r"(a[3]), "r"(b0), "r"(b1));
}
__device__ __forceinline__ uint32_t pack_h2(float x, float y) {
    __half2 h = __floats2half2_rn(x, y);
    return *(uint32_t*)&h;
}

/* ================= fp16 conversion kernels =============================== */
__global__ __launch_bounds__(256) void conv_rows(const float* __restrict__ src,
                                                 __half* __restrict__ dst) {
    size_t idx = (size_t)blockIdx.x * 256 + threadIdx.x;
    float2 v = ((const float2*)src)[idx];
    ((uint32_t*)dst)[idx] = pack_h2(v.x, v.y);
}
__global__ __launch_bounds__(256) void conv_wt(const float* __restrict__ src,
                                               __half* __restrict__ dst, int N) {
    __shared__ float t[32][33];
    int kb = blockIdx.x * 32, nb = blockIdx.y * 32;
    int tx = threadIdx.x, ty = threadIdx.y;
#pragma unroll
    for (int i = 0; i < 32; i += 8)
        t[ty + i][tx] = src[(size_t)(kb + ty + i) * N + nb + tx];
    __syncthreads();
#pragma unroll
    for (int i = 0; i < 32; i += 8) {
        int n = nb + ty + i, k = kb + tx;
        dst[(size_t)n * KW + k] = __float2half_rn(t[tx][ty + i]);
    }
}

/* ========== mma.sync fp16 GEMM (R11-validated shape, 256 thr) ============ */
#define TILE_BYTES 16384

__global__ __launch_bounds__(256) void gemm_mma(const __half* __restrict__ A,
                                                const __half* __restrict__ B,
                                                float* __restrict__ C, int N) {
    extern __shared__ char smc[];
    const uint32_t smb = smem_u32(smc);
    const int tid  = threadIdx.x;
    const int lane = tid & 31;
    const int wid  = tid >> 5;
    const int wm   = wid & 1;
    const int wn   = wid >> 1;
    const int m0   = blockIdx.x * 128;
    const int n0   = blockIdx.y * 128;

    const uint32_t sA[2] = { smb,              smb + 2*TILE_BYTES };
    const uint32_t sB[2] = { smb + TILE_BYTES, smb + 3*TILE_BYTES };

    const int r    = tid >> 1;
    const int halfc= tid & 1;
    const __half* gA = A + (size_t)(m0 + r) * KW + halfc * 32;
    const __half* gB = B + (size_t)(n0 + r) * KW + halfc * 32;
    const uint32_t soff[4] = {
        sw128((uint32_t)r * 128u + (uint32_t)(halfc * 4 + 0) * 16u),
        sw128((uint32_t)r * 128u + (uint32_t)(halfc * 4 + 1) * 16u),
        sw128((uint32_t)r * 128u + (uint32_t)(halfc * 4 + 2) * 16u),
        sw128((uint32_t)r * 128u + (uint32_t)(halfc * 4 + 3) * 16u) };

    float acc[4][4][4];
#pragma unroll
    for (int i = 0; i < 4; i++)
#pragma unroll
        for (int j = 0; j < 4; j++)
#pragma unroll
            for (int q = 0; q < 4; q++) acc[i][j][q] = 0.0f;

    const int arow = wm * 64 + (lane & 15);
    const int brow = wn * 32 + (lane & 15);
    const int kc   = lane >> 4;

#pragma unroll
    for (int p = 0; p < 2; p++) {
        const __half* pa = gA + (size_t)p * KTILE;
        const __half* pb = gB + (size_t)p * KTILE;
#pragma unroll
        for (int j = 0; j < 4; j++) {
            cp_async16(sA[p] + soff[j], pa + j * 8);
            cp_async16(sB[p] + soff[j], pb + j * 8);
        }
        CP_COMMIT();
    }

    for (int it = 0; it < KITER; ++it) {
        const int s = it & 1;
        if (it + 1 < KITER) CP_WAIT(1); else CP_WAIT(0);
        __syncthreads();

#pragma unroll
        for (int ks = 0; ks < 4; ks++) {
            uint32_t aF[4][4], bF[2][4];
            const uint32_t acol = (uint32_t)(ks * 2 + kc) * 16u;
#pragma unroll
            for (int mt = 0; mt < 4; mt++)
                ldsm_x4(aF[mt], sA[s] + sw128((uint32_t)(arow + mt * 16) * 128u + acol));
            ldsm_x4(bF[0], sB[s] + sw128((uint32_t)(brow)      * 128u + acol));
            ldsm_x4(bF[1], sB[s] + sw128((uint32_t)(brow + 16) * 128u + acol));
#pragma unroll
            for (int mt = 0; mt < 4; mt++)
#pragma unroll
                for (int nt = 0; nt < 4; nt++) {
                    const int gsel = nt >> 1, sub = nt & 1;
                    mma16816(acc[mt][nt], aF[mt], bF[gsel][sub], bF[gsel][sub + 2]);
                }
        }
        __syncthreads();

        if (it + 2 < KITER) {
            const int sn = s;
            const __half* pa = gA + (size_t)(it + 2) * KTILE;
            const __half* pb = gB + (size_t)(it + 2) * KTILE;
#pragma unroll
            for (int j = 0; j < 4; j++) {
                cp_async16(sA[sn] + soff[j], pa + j * 8);
                cp_async16(sB[sn] + soff[j], pb + j * 8);
            }
            CP_COMMIT();
        }
    }

#pragma unroll
    for (int mt = 0; mt < 4; mt++) {
        const int row0 = m0 + wm * 64 + mt * 16 + (lane >> 2);
#pragma unroll
        for (int nt = 0; nt < 4; nt++) {
            const int col = n0 + wn * 32 + nt * 8 + (lane & 3) * 2;
            float2 lo = { acc[mt][nt][0], acc[mt][nt][1] };
            float2 hi = { acc[mt][nt][2], acc[mt][nt][3] };
            *(float2*)(C + (size_t)row0 * N + col)       = lo;
            *(float2*)(C + (size_t)(row0 + 8) * N + col) = hi;
        }
    }
}

/* -------- RoPE -> fp16 Q/K layouts + V fp16 transpose [g][d][s] ---------- */
__global__ __launch_bounds__(256) void rope_split(const int* __restrict__ positions) {
    const int s = blockIdx.x;
    const float* row = g_qkv + (size_t)s * QKV_N;
    const float pos = (float)positions[s];
    const int tid = threadIdx.x;
    const float LN_THETA_OVER_HALF = 9.210340371976184f / 64.0f;

    for (int idx = tid; idx < NQ * HALF; idx += 256) {
        int h = idx >> 6, j = idx & 63;
        float inv = expf(-(float)j * LN_THETA_OVER_HALF);
        float f = pos * inv;
        float c = cosf(f), sn = sinf(f);
        float x1 = row[h * HD + j];
        float x2 = row[h * HD + HALF + j];
        __half* o = g_qh + ((size_t)h * S_LEN + s) * HD;
        o[j]        = __float2half_rn(x1 * c - x2 * sn);
        o[HALF + j] = __float2half_rn(x2 * c + x1 * sn);
    }
    for (int idx = tid; idx < NKV * HALF; idx += 256) {
        int h = idx >> 6, j = idx & 63;
        float inv = expf(-(float)j * LN_THETA_OVER_HALF);
        float f = pos * inv;
        float c = cosf(f), sn = sinf(f);
        const float* kr = row + NQ * HD;
        float x1 = kr[h * HD + j];
        float x2 = kr[h * HD + HALF + j];
        __half* o = g_kh + ((size_t)h * S_LEN + s) * HD;
        o[j]        = __float2half_rn(x1 * c - x2 * sn);
        o[HALF + j] = __float2half_rn(x2 * c + x1 * sn);
    }
    for (int idx = tid; idx < NKV * HD; idx += 256) {
        int g = idx >> 7, d = idx & 127;
        float x = row[NQ * HD + NKV * HD + g * HD + d];
        g_vh[((size_t)g * HD + d) * S_LEN + s] = __float2half_rn(x);
    }
}

/* ======== tensor-core flash attention: Br=128, Bc=64, causal, fp16 ======= */
#define AS_Q    0
#define AS_K0   32768
#define AS_V0   (AS_K0 + 16384)
#define AS_K1   (AS_V0 + 16384)
#define AS_V1   (AS_K1 + 16384)
#define AS_KP   (AS_V1 + 16384)
#define AS_TOT  (AS_KP + 512)

__global__ __launch_bounds__(256) void attn_mma(const int* __restrict__ positions) {
    extern __shared__ char smc[];
    const uint32_t smb = smem_u32(smc);
    int* kp = (int*)(smc + AS_KP);

    const int h  = blockIdx.y;
    const int qt = 31 - blockIdx.x;
    const int g  = h / GRP;
    const int tid  = threadIdx.x;
    const int lane = tid & 31;
    const int w    = tid >> 5;
    const int kc   = lane >> 4;

    const uint32_t sK[2] = { smb + AS_K0, smb + AS_K1 };
    const uint32_t sV[2] = { smb + AS_V0, smb + AS_V1 };

    const __half* qg = g_qh + ((size_t)h * S_LEN + (size_t)qt * 128) * HD;
    for (int c = tid; c < 2048; c += 256) {
        int s = c >> 4, cc = c & 15;
        uint32_t dst = smb + AS_Q +
            sw128((uint32_t)(s * 2 + (cc >> 3)) * 128u + (uint32_t)(cc & 7) * 16u);
        cp_async16(dst, (const char*)qg + (size_t)c * 16);
    }

    const __half* kgb = g_kh + (size_t)g * S_LEN * HD;
    const __half* vgb = g_vh + (size_t)g * HD * S_LEN;

    const int ntiles = 2 * qt + 2;
#define LOAD_KV(st, kt_)  do {                                                \
        const __half* kg_ = kgb + (size_t)(kt_) * 64 * HD;                    \
        for (int c = tid; c < 1024; c += 256) {                               \
            int s_ = c >> 4, cc_ = c & 15;                                    \
            uint32_t dst_ = sK[st] +                                          \
                sw128((uint32_t)(s_ * 2 + (cc_ >> 3)) * 128u +                \
                      (uint32_t)(cc_ & 7) * 16u);                             \
            cp_async16(dst_, (const char*)kg_ + (size_t)c * 16);              \
        }                                                                     \
        for (int c = tid; c < 1024; c += 256) {                               \
            int d_ = c >> 3, j_ = c & 7;                                      \
            uint32_t dst_ = sV[st] + sw128((uint32_t)d_ * 128u +              \
                                           (uint32_t)j_ * 16u);               \
            cp_async16(dst_, (const char*)(vgb + (size_t)d_ * S_LEN +         \
                                           (size_t)(kt_) * 64) + j_ * 16);    \
        }                                                                     \
        if (tid < 64) kp[(st) * 64 + tid] = positions[(kt_) * 64 + tid];      \
    } while (0)

    LOAD_KV(0, 0);
    CP_COMMIT();

    const int qr = qt * 128 + w * 16 + (lane >> 2);
    const int qpos0 = positions[qr];
    const int qpos1 = positions[qr + 8];

    float m_i[2] = { -1e30f, -1e30f };
    float l_i[2] = { 0.0f, 0.0f };
    float acc[16][4];
#pragma unroll
    for (int t = 0; t < 16; t++)
#pragma unroll
        for (int q = 0; q < 4; q++) acc[t][q] = 0.0f;

    for (int kt = 0; kt < ntiles; kt++) {
        const int st = kt & 1;
        CP_WAIT(0);
        __syncthreads();

        if (kt + 1 < ntiles) {
            LOAD_KV(st ^ 1, kt + 1);
            CP_COMMIT();
        }

        float sc[8][4];
#pragma unroll
        for (int j = 0; j < 8; j++)
#pragma unroll
            for (int q = 0; q < 4; q++) sc[j][q] = 0.0f;

#pragma unroll
        for (int ks = 0; ks < 8; ks++) {
            const int cc = 2 * ks + kc;
            uint32_t aF[4];
            {
                int m = w * 16 + (lane & 15);
                ldsm_x4(aF, smb + AS_Q +
                    sw128((uint32_t)(m * 2 + (cc >> 3)) * 128u + (uint32_t)(cc & 7) * 16u));
            }
#pragma unroll
            for (int grp = 0; grp < 4; grp++) {
                uint32_t bF[4];
                int kv = grp * 16 + (lane & 15);
                ldsm_x4(bF, sK[st] +
                    sw128((uint32_t)(kv * 2 + (cc >> 3)) * 128u + (uint32_t)(cc & 7) * 16u));
                mma16816(sc[grp * 2 + 0], aF, bF[0], bF[2]);
                mma16816(sc[grp * 2 + 1], aF, bF[1], bF[3]);
            }
        }

#pragma unroll
        for (int j = 0; j < 8; j++) {
            int kcol = j * 8 + 2 * (lane & 3);
            int kp0 = kp[st * 64 + kcol], kp1 = kp[st * 64 + kcol + 1];
            float s0 = sc[j][0] * ATT_SCALE, s1 = sc[j][1] * ATT_SCALE;
            float s2 = sc[j][2] * ATT_SCALE, s3 = sc[j][3] * ATT_SCALE;
            sc[j][0] = (qpos0 >= kp0) ? s0 : -1e30f;
            sc[j][1] = (qpos0 >= kp1) ? s1 : -1e30f;
            sc[j][2] = (qpos1 >= kp0) ? s2 : -1e30f;
            sc[j][3] = (qpos1 >= kp1) ? s3 : -1e30f;
        }

        float mt0 = -1e30f, mt1 = -1e30f;
#pragma unroll
        for (int j = 0; j < 8; j++) {
            mt0 = fmaxf(mt0, fmaxf(sc[j][0], sc[j][1]));
            mt1 = fmaxf(mt1, fmaxf(sc[j][2], sc[j][3]));
        }
        mt0 = fmaxf(mt0, __shfl_xor_sync(0xffffffffu, mt0, 1));
        mt0 = fmaxf(mt0, __shfl_xor_sync(0xffffffffu, mt0, 2));
        mt1 = fmaxf(mt1, __shfl_xor_sync(0xffffffffu, mt1, 1));
        mt1 = fmaxf(mt1, __shfl_xor_sync(0xffffffffu, mt1, 2));

        float mn0 = fmaxf(m_i[0], mt0), mn1 = fmaxf(m_i[1], mt1);
        float al0 = __expf(m_i[0] - mn0), al1 = __expf(m_i[1] - mn1);
        m_i[0] = mn0; m_i[1] = mn1;

        float rs0 = 0.0f, rs1 = 0.0f;
#pragma unroll
        for (int j = 0; j < 8; j++) {
            sc[j][0] = __expf(sc[j][0] - mn0);
            sc[j][1] = __expf(sc[j][1] - mn0);
            sc[j][2] = __expf(sc[j][2] - mn1);
            sc[j][3] = __expf(sc[j][3] - mn1);
            rs0 += sc[j][0] + sc[j][1];
            rs1 += sc[j][2] + sc[j][3];
        }
        rs0 += __shfl_xor_sync(0xffffffffu, rs0, 1);
        rs0 += __shfl_xor_sync(0xffffffffu, rs0, 2);
        rs1 += __shfl_xor_sync(0xffffffffu, rs1, 1);
        rs1 += __shfl_xor_sync(0xffffffffu, rs1, 2);
        l_i[0] = l_i[0] * al0 + rs0;
        l_i[1] = l_i[1] * al1 + rs1;

#pragma unroll
        for (int t = 0; t < 16; t++) {
            acc[t][0] *= al0; acc[t][1] *= al0;
            acc[t][2] *= al1; acc[t][3] *= al1;
        }

#pragma unroll
        for (int ks = 0; ks < 4; ks++) {
            const int j0 = 2 * ks, j1 = 2 * ks + 1;
            uint32_t ahi[4], alo[4];
            ahi[0] = pack_h2(sc[j0][0], sc[j0][1]);
            ahi[1] = pack_h2(sc[j0][2], sc[j0][3]);
            ahi[2] = pack_h2(sc[j1][0], sc[j1][1]);
            ahi[3] = pack_h2(sc[j1][2], sc[j1][3]);
            {
                __half2* hp;
                hp = (__half2*)&ahi[0];
                alo[0] = pack_h2(sc[j0][0] - __half2float(hp->x),
                                 sc[j0][1] - __half2float(hp->y));
                hp = (__half2*)&ahi[1];
                alo[1] = pack_h2(sc[j0][2] - __half2float(hp->x),
                                 sc[j0][3] - __half2float(hp->y));
                hp = (__half2*)&ahi[2];
                alo[2] = pack_h2(sc[j1][0] - __half2float(hp->x),
                                 sc[j1][1] - __half2float(hp->y));
                hp = (__half2*)&ahi[3];
                alo[3] = pack_h2(sc[j1][2] - __half2float(hp->x),
                                 sc[j1][3] - __half2float(hp->y));
            }
            const uint32_t ccol = (uint32_t)(2 * ks + kc) * 16u;
#pragma unroll
            for (int grp = 0; grp < 8; grp++) {
                uint32_t vh[4];
                uint32_t roff = sw128((uint32_t)(grp * 16 + (lane & 15)) * 128u + ccol);
                ldsm_x4(vh, sV[st] + roff);
                const int t0 = grp * 2, t1 = grp * 2 + 1;
                mma16816(acc[t0], ahi, vh[0], vh[2]);
                mma16816(acc[t1], ahi, vh[1], vh[3]);
                mma16816(acc[t0], alo, vh[0], vh[2]);
                mma16816(acc[t1], alo, vh[1], vh[3]);
            }
        }
        __syncthreads();
    }

    /* ---- epilogue: normalize + write fp16 into g_Ah --------------------- */
    float inv0 = 1.0f / l_i[0];
    float inv1 = 1.0f / l_i[1];
    const size_t base0 = (size_t)qr * HID;
    const size_t base1 = (size_t)(qr + 8) * HID;
#pragma unroll
    for (int t = 0; t < 16; t++) {
        int col = h * HD + t * 8 + (lane & 3) * 2;
        *(uint32_t*)(g_Ah + base0 + col) =
            pack_h2(acc[t][0] * inv0, acc[t][1] * inv0);
        *(uint32_t*)(g_Ah + base1 + col) =
            pack_h2(acc[t][2] * inv1, acc[t][3] * inv1);
    }
}

/* ------------------------------- launch ---------------------------------- */
extern "C" void kernel_launch(void* const* d_in, const int* in_sizes, int n_in,
                              void* d_out, int out_size) {
    const int*   positions = (const int*)  d_in[0];
    const float* hidden    = (const float*)d_in[1];
    const float* w_qkv     = (const float*)d_in[2];
    const float* w_o       = (const float*)d_in[3];
    float*       out       = (float*)d_out;
    (void)in_sizes; (void)n_in; (void)out_size;

    void *p_qkv = nullptr, *p_xh = nullptr, *p_ah = nullptr,
         *p_wq = nullptr, *p_wo = nullptr;
    cudaGetSymbolAddress(&p_qkv, g_qkv);
    cudaGetSymbolAddress(&p_xh,  g_Xh);
    cudaGetSymbolAddress(&p_ah,  g_Ah);
    cudaGetSymbolAddress(&p_wq,  g_Wq);
    cudaGetSymbolAddress(&p_wo,  g_Wo);

    const int gemm_smem = 4 * TILE_BYTES;   /* 64 KB */
    cudaFuncSetAttribute(gemm_mma, cudaFuncAttributeMaxDynamicSharedMemorySize,
                         gemm_smem);
    cudaFuncSetAttribute(attn_mma, cudaFuncAttributeMaxDynamicSharedMemorySize,
                         AS_TOT);

    /* 0) fp16 conversions (hi only) */
    conv_rows<<<(S_LEN * HID / 2) / 256, 256>>>(hidden, (__half*)p_xh);
    conv_wt<<<dim3(HID / 32, QKV_N / 32), dim3(32, 8)>>>(w_qkv, (__half*)p_wq, QKV_N);
    conv_wt<<<dim3(HID / 32, HID / 32), dim3(32, 8)>>>(w_o, (__half*)p_wo, HID);

    /* 1) QKV projection: 1-term fp16 (K=4096) */
    gemm_mma<<<dim3(S_LEN / 128, QKV_N / 128), 256, gemm_smem>>>(
        (const __half*)p_xh, (const __half*)p_wq, (float*)p_qkv, QKV_N);

    /* 2) RoPE -> fp16 Q/K + V fp16 transpose */
    rope_split<<<S_LEN, 256>>>(positions);

    /* 3) tensor-core flash attention (double-buffered K/V) */
    attn_mma<<<dim3(32, NQ), 256, AS_TOT>>>(positions);

    /* 4) output projection: 1-term fp16 (K=4096) */
    gemm_mma<<<dim3(S_LEN / 128, HID / 128), 256, gemm_smem>>>(
        (const __half*)p_ah, (const __half*)p_wo, out, HID);
}

// round 17
// speedup vs baseline: 2.3318x; 1.0809x over previous
#include <cuda_runtime.h>
#include <cuda_fp16.h>
#include <cstdint>
#include <cstddef>

#define S_LEN 4096
#define HID   4096
#define NQ    32
#define NKV   8
#define HD    128
#define HALF  64
#define GRP   4
#define QKV_N (NQ*HD + 2*NKV*HD)   /* 6144 */
#define ATT_SCALE 0.08838834764831845f
#define KW    HID                  /* 4096 */
#define KTILE 64
#define KITER (KW/KTILE)           /* 64 */

/* ---------------- scratch (device globals: allocation-free) -------------- */
__device__ float  g_qkv[(size_t)S_LEN * QKV_N];
__device__ __half g_qh [(size_t)NQ  * S_LEN * HD];   /* roped Q fp16 [h][s][d] */
__device__ __half g_kh [(size_t)NKV * S_LEN * HD];   /* roped K fp16 [g][s][d] */
__device__ __half g_vh [(size_t)NKV * HD * S_LEN];   /* V fp16 [g][d][s]       */
__device__ __half g_Xh [(size_t)S_LEN * HID];        /* hidden fp16 (hi)       */
__device__ __half g_Ah [(size_t)S_LEN * HID];        /* attention out fp16     */
__device__ __half g_Wq [(size_t)QKV_N * KW];
__device__ __half g_Wo [(size_t)HID   * KW];

/* ======================= small asm helpers =============================== */
__device__ __forceinline__ uint32_t smem_u32(const void* p) {
    uint32_t a;
    asm("{ .reg .u64 t; cvta.to.shared.u64 t, %1; cvt.u32.u64 %0, t; }"
        : "=r"(a) : "l"(p));
    return a;
}
__device__ __forceinline__ uint32_t sw128(uint32_t off) {   /* Swizzle<3,4,3> */
    return off ^ ((off >> 3) & 0x70);
}
__device__ __forceinline__ void cp_async16(uint32_t saddr, const void* gaddr) {
    asm volatile("cp.async.cg.shared.global [%0], [%1], 16;"
                 :: "r"(saddr), "l"(gaddr));
}
#define CP_COMMIT() asm volatile("cp.async.commit_group;" ::: "memory")
#define CP_WAIT(n)  asm volatile("cp.async.wait_group %0;" :: "n"(n) : "memory")

__device__ __forceinline__ void ldsm_x4(uint32_t* f, uint32_t addr) {
    asm volatile("ldmatrix.sync.aligned.m8n8.x4.shared.b16 {%0,%1,%2,%3}, [%4];"
                 : "=r"(f[0]), "=r"(f[1]), "=r"(f[2]), "=r"(f[3]) : "r"(addr));
}
__device__ __forceinline__ void mma16816(float* d, const uint32_t* a,
                                         uint32_t b0, uint32_t b1) {
    asm volatile("mma.sync.aligned.m16n8k16.row.col.f32.f16.f16.f32 "
                 "{%0,%1,%2,%3}, {%4,%5,%6,%7}, {%8,%9}, {%0,%1,%2,%3};"
                 : "+f"(d[0]), "+f"(d[1]), "+f"(d[2]), "+f"(d[3])
                 : "r"(a[0]), "r"(a[1]), "r"(a[2]), "r"(a[3]), "r"(b0), "r"(b1));
}
__device__ __forceinline__ uint32_t pack_h2(float x, float y) {
    __half2 h = __floats2half2_rn(x, y);
    return *(uint32_t*)&h;
}

/* ================= fp16 conversion kernels =============================== */
__global__ __launch_bounds__(256) void conv_rows(const float* __restrict__ src,
                                                 __half* __restrict__ dst) {
    size_t idx = (size_t)blockIdx.x * 256 + threadIdx.x;
    float2 v = ((const float2*)src)[idx];
    ((uint32_t*)dst)[idx] = pack_h2(v.x, v.y);
}
__global__ __launch_bounds__(256) void conv_wt(const float* __restrict__ src,
                                               __half* __restrict__ dst, int N) {
    __shared__ float t[32][33];
    int kb = blockIdx.x * 32, nb = blockIdx.y * 32;
    int tx = threadIdx.x, ty = threadIdx.y;
#pragma unroll
    for (int i = 0; i < 32; i += 8)
        t[ty + i][tx] = src[(size_t)(kb + ty + i) * N + nb + tx];
    __syncthreads();
#pragma unroll
    for (int i = 0; i < 32; i += 8) {
        int n = nb + ty + i, k = kb + tx;
        dst[(size_t)n * KW + k] = __float2half_rn(t[tx][ty + i]);
    }
}

/* ========== mma.sync fp16 GEMM (R11-validated shape, 256 thr) ============ */
#define TILE_BYTES 16384

__global__ __launch_bounds__(256) void gemm_mma(const __half* __restrict__ A,
                                                const __half* __restrict__ B,
                                                float* __restrict__ C, int N) {
    extern __shared__ char smc[];
    const uint32_t smb = smem_u32(smc);
    const int tid  = threadIdx.x;
    const int lane = tid & 31;
    const int wid  = tid >> 5;
    const int wm   = wid & 1;
    const int wn   = wid >> 1;
    const int m0   = blockIdx.x * 128;
    const int n0   = blockIdx.y * 128;

    const uint32_t sA[2] = { smb,              smb + 2*TILE_BYTES };
    const uint32_t sB[2] = { smb + TILE_BYTES, smb + 3*TILE_BYTES };

    const int r    = tid >> 1;
    const int halfc= tid & 1;
    const __half* gA = A + (size_t)(m0 + r) * KW + halfc * 32;
    const __half* gB = B + (size_t)(n0 + r) * KW + halfc * 32;
    const uint32_t soff[4] = {
        sw128((uint32_t)r * 128u + (uint32_t)(halfc * 4 + 0) * 16u),
        sw128((uint32_t)r * 128u + (uint32_t)(halfc * 4 + 1) * 16u),
        sw128((uint32_t)r * 128u + (uint32_t)(halfc * 4 + 2) * 16u),
        sw128((uint32_t)r * 128u + (uint32_t)(halfc * 4 + 3) * 16u) };

    float acc[4][4][4];
#pragma unroll
    for (int i = 0; i < 4; i++)
#pragma unroll
        for (int j = 0; j < 4; j++)
#pragma unroll
            for (int q = 0; q < 4; q++) acc[i][j][q] = 0.0f;

    const int arow = wm * 64 + (lane & 15);
    const int brow = wn * 32 + (lane & 15);
    const int kc   = lane >> 4;

#pragma unroll
    for (int p = 0; p < 2; p++) {
        const __half* pa = gA + (size_t)p * KTILE;
        const __half* pb = gB + (size_t)p * KTILE;
#pragma unroll
        for (int j = 0; j < 4; j++) {
            cp_async16(sA[p] + soff[j], pa + j * 8);
            cp_async16(sB[p] + soff[j], pb + j * 8);
        }
        CP_COMMIT();
    }

    for (int it = 0; it < KITER; ++it) {
        const int s = it & 1;
        if (it + 1 < KITER) CP_WAIT(1); else CP_WAIT(0);
        __syncthreads();

#pragma unroll
        for (int ks = 0; ks < 4; ks++) {
            uint32_t aF[4][4], bF[2][4];
            const uint32_t acol = (uint32_t)(ks * 2 + kc) * 16u;
#pragma unroll
            for (int mt = 0; mt < 4; mt++)
                ldsm_x4(aF[mt], sA[s] + sw128((uint32_t)(arow + mt * 16) * 128u + acol));
            ldsm_x4(bF[0], sB[s] + sw128((uint32_t)(brow)      * 128u + acol));
            ldsm_x4(bF[1], sB[s] + sw128((uint32_t)(brow + 16) * 128u + acol));
#pragma unroll
            for (int mt = 0; mt < 4; mt++)
#pragma unroll
                for (int nt = 0; nt < 4; nt++) {
                    const int gsel = nt >> 1, sub = nt & 1;
                    mma16816(acc[mt][nt], aF[mt], bF[gsel][sub], bF[gsel][sub + 2]);
                }
        }
        __syncthreads();

        if (it + 2 < KITER) {
            const int sn = s;
            const __half* pa = gA + (size_t)(it + 2) * KTILE;
            const __half* pb = gB + (size_t)(it + 2) * KTILE;
#pragma unroll
            for (int j = 0; j < 4; j++) {
                cp_async16(sA[sn] + soff[j], pa + j * 8);
                cp_async16(sB[sn] + soff[j], pb + j * 8);
            }
            CP_COMMIT();
        }
    }

#pragma unroll
    for (int mt = 0; mt < 4; mt++) {
        const int row0 = m0 + wm * 64 + mt * 16 + (lane >> 2);
#pragma unroll
        for (int nt = 0; nt < 4; nt++) {
            const int col = n0 + wn * 32 + nt * 8 + (lane & 3) * 2;
            float2 lo = { acc[mt][nt][0], acc[mt][nt][1] };
            float2 hi = { acc[mt][nt][2], acc[mt][nt][3] };
            *(float2*)(C + (size_t)row0 * N + col)       = lo;
            *(float2*)(C + (size_t)(row0 + 8) * N + col) = hi;
        }
    }
}

/* -------- RoPE -> fp16 Q/K layouts + V fp16 transpose [g][d][s] ---------- */
__global__ __launch_bounds__(256) void rope_split(const int* __restrict__ positions) {
    const int s = blockIdx.x;
    const float* row = g_qkv + (size_t)s * QKV_N;
    const float pos = (float)positions[s];
    const int tid = threadIdx.x;
    const float LN_THETA_OVER_HALF = 9.210340371976184f / 64.0f;

    for (int idx = tid; idx < NQ * HALF; idx += 256) {
        int h = idx >> 6, j = idx & 63;
        float inv = expf(-(float)j * LN_THETA_OVER_HALF);
        float f = pos * inv;
        float c = cosf(f), sn = sinf(f);
        float x1 = row[h * HD + j];
        float x2 = row[h * HD + HALF + j];
        __half* o = g_qh + ((size_t)h * S_LEN + s) * HD;
        o[j]        = __float2half_rn(x1 * c - x2 * sn);
        o[HALF + j] = __float2half_rn(x2 * c + x1 * sn);
    }
    for (int idx = tid; idx < NKV * HALF; idx += 256) {
        int h = idx >> 6, j = idx & 63;
        float inv = expf(-(float)j * LN_THETA_OVER_HALF);
        float f = pos * inv;
        float c = cosf(f), sn = sinf(f);
        const float* kr = row + NQ * HD;
        float x1 = kr[h * HD + j];
        float x2 = kr[h * HD + HALF + j];
        __half* o = g_kh + ((size_t)h * S_LEN + s) * HD;
        o[j]        = __float2half_rn(x1 * c - x2 * sn);
        o[HALF + j] = __float2half_rn(x2 * c + x1 * sn);
    }
    for (int idx = tid; idx < NKV * HD; idx += 256) {
        int g = idx >> 7, d = idx & 127;
        float x = row[NQ * HD + NKV * HD + g * HD + d];
        g_vh[((size_t)g * HD + d) * S_LEN + s] = __float2half_rn(x);
    }
}

/* ======== tensor-core flash attention: Br=128, Bc=64, causal, fp16 ======= */
#define AS_Q    0
#define AS_K0   32768
#define AS_V0   (AS_K0 + 16384)
#define AS_K1   (AS_V0 + 16384)
#define AS_V1   (AS_K1 + 16384)
#define AS_KP   (AS_V1 + 16384)
#define AS_TOT  (AS_KP + 512)

__global__ __launch_bounds__(256) void attn_mma(const int* __restrict__ positions) {
    extern __shared__ char smc[];
    const uint32_t smb = smem_u32(smc);
    int* kp = (int*)(smc + AS_KP);

    const int h  = blockIdx.y;
    const int qt = 31 - blockIdx.x;
    const int g  = h / GRP;
    const int tid  = threadIdx.x;
    const int lane = tid & 31;
    const int w    = tid >> 5;
    const int kc   = lane >> 4;

    const uint32_t sK[2] = { smb + AS_K0, smb + AS_K1 };
    const uint32_t sV[2] = { smb + AS_V0, smb + AS_V1 };

    const __half* qg = g_qh + ((size_t)h * S_LEN + (size_t)qt * 128) * HD;
    for (int c = tid; c < 2048; c += 256) {
        int s = c >> 4, cc = c & 15;
        uint32_t dst = smb + AS_Q +
            sw128((uint32_t)(s * 2 + (cc >> 3)) * 128u + (uint32_t)(cc & 7) * 16u);
        cp_async16(dst, (const char*)qg + (size_t)c * 16);
    }

    const __half* kgb = g_kh + (size_t)g * S_LEN * HD;
    const __half* vgb = g_vh + (size_t)g * HD * S_LEN;

    const int ntiles = 2 * qt + 2;
#define LOAD_KV(st, kt_)  do {                                                \
        const __half* kg_ = kgb + (size_t)(kt_) * 64 * HD;                    \
        for (int c = tid; c < 1024; c += 256) {                               \
            int s_ = c >> 4, cc_ = c & 15;                                    \
            uint32_t dst_ = sK[st] +                                          \
                sw128((uint32_t)(s_ * 2 + (cc_ >> 3)) * 128u +                \
                      (uint32_t)(cc_ & 7) * 16u);                             \
            cp_async16(dst_, (const char*)kg_ + (size_t)c * 16);              \
        }                                                                     \
        for (int c = tid; c < 1024; c += 256) {                               \
            int d_ = c >> 3, j_ = c & 7;                                      \
            uint32_t dst_ = sV[st] + sw128((uint32_t)d_ * 128u +              \
                                           (uint32_t)j_ * 16u);               \
            cp_async16(dst_, (const char*)(vgb + (size_t)d_ * S_LEN +         \
                                           (size_t)(kt_) * 64) + j_ * 16);    \
        }                                                                     \
        if (tid < 64) kp[(st) * 64 + tid] = positions[(kt_) * 64 + tid];      \
    } while (0)

    LOAD_KV(0, 0);
    CP_COMMIT();

    const int qr = qt * 128 + w * 16 + (lane >> 2);
    const int qpos0 = positions[qr];
    const int qpos1 = positions[qr + 8];

    float m_i[2] = { -1e30f, -1e30f };
    float l_i[2] = { 0.0f, 0.0f };
    float acc[16][4];
#pragma unroll
    for (int t = 0; t < 16; t++)
#pragma unroll
        for (int q = 0; q < 4; q++) acc[t][q] = 0.0f;

    for (int kt = 0; kt < ntiles; kt++) {
        const int st = kt & 1;
        CP_WAIT(0);
        __syncthreads();

        if (kt + 1 < ntiles) {
            LOAD_KV(st ^ 1, kt + 1);
            CP_COMMIT();
        }

        float sc[8][4];
#pragma unroll
        for (int j = 0; j < 8; j++)
#pragma unroll
            for (int q = 0; q < 4; q++) sc[j][q] = 0.0f;

#pragma unroll
        for (int ks = 0; ks < 8; ks++) {
            const int cc = 2 * ks + kc;
            uint32_t aF[4];
            {
                int m = w * 16 + (lane & 15);
                ldsm_x4(aF, smb + AS_Q +
                    sw128((uint32_t)(m * 2 + (cc >> 3)) * 128u + (uint32_t)(cc & 7) * 16u));
            }
#pragma unroll
            for (int grp = 0; grp < 4; grp++) {
                uint32_t bF[4];
                int kv = grp * 16 + (lane & 15);
                ldsm_x4(bF, sK[st] +
                    sw128((uint32_t)(kv * 2 + (cc >> 3)) * 128u + (uint32_t)(cc & 7) * 16u));
                mma16816(sc[grp * 2 + 0], aF, bF[0], bF[2]);
                mma16816(sc[grp * 2 + 1], aF, bF[1], bF[3]);
            }
        }

#pragma unroll
        for (int j = 0; j < 8; j++) {
            int kcol = j * 8 + 2 * (lane & 3);
            int kp0 = kp[st * 64 + kcol], kp1 = kp[st * 64 + kcol + 1];
            float s0 = sc[j][0] * ATT_SCALE, s1 = sc[j][1] * ATT_SCALE;
            float s2 = sc[j][2] * ATT_SCALE, s3 = sc[j][3] * ATT_SCALE;
            sc[j][0] = (qpos0 >= kp0) ? s0 : -1e30f;
            sc[j][1] = (qpos0 >= kp1) ? s1 : -1e30f;
            sc[j][2] = (qpos1 >= kp0) ? s2 : -1e30f;
            sc[j][3] = (qpos1 >= kp1) ? s3 : -1e30f;
        }

        float mt0 = -1e30f, mt1 = -1e30f;
#pragma unroll
        for (int j = 0; j < 8; j++) {
            mt0 = fmaxf(mt0, fmaxf(sc[j][0], sc[j][1]));
            mt1 = fmaxf(mt1, fmaxf(sc[j][2], sc[j][3]));
        }
        mt0 = fmaxf(mt0, __shfl_xor_sync(0xffffffffu, mt0, 1));
        mt0 = fmaxf(mt0, __shfl_xor_sync(0xffffffffu, mt0, 2));
        mt1 = fmaxf(mt1, __shfl_xor_sync(0xffffffffu, mt1, 1));
        mt1 = fmaxf(mt1, __shfl_xor_sync(0xffffffffu, mt1, 2));

        float mn0 = fmaxf(m_i[0], mt0), mn1 = fmaxf(m_i[1], mt1);
        float al0 = __expf(m_i[0] - mn0), al1 = __expf(m_i[1] - mn1);
        m_i[0] = mn0; m_i[1] = mn1;

        float rs0 = 0.0f, rs1 = 0.0f;
#pragma unroll
        for (int j = 0; j < 8; j++) {
            sc[j][0] = __expf(sc[j][0] - mn0);
            sc[j][1] = __expf(sc[j][1] - mn0);
            sc[j][2] = __expf(sc[j][2] - mn1);
            sc[j][3] = __expf(sc[j][3] - mn1);
            rs0 += sc[j][0] + sc[j][1];
            rs1 += sc[j][2] + sc[j][3];
        }
        rs0 += __shfl_xor_sync(0xffffffffu, rs0, 1);
        rs0 += __shfl_xor_sync(0xffffffffu, rs0, 2);
        rs1 += __shfl_xor_sync(0xffffffffu, rs1, 1);
        rs1 += __shfl_xor_sync(0xffffffffu, rs1, 2);
        l_i[0] = l_i[0] * al0 + rs0;
        l_i[1] = l_i[1] * al1 + rs1;

#pragma unroll
        for (int t = 0; t < 16; t++) {
            acc[t][0] *= al0; acc[t][1] *= al0;
            acc[t][2] *= al1; acc[t][3] *= al1;
        }

        /* ---- PV: acc += P_hi * Vh  (P_lo term dropped; ~1.4e-4 rel) ---- */
#pragma unroll
        for (int ks = 0; ks < 4; ks++) {
            const int j0 = 2 * ks, j1 = 2 * ks + 1;
            uint32_t ahi[4];
            ahi[0] = pack_h2(sc[j0][0], sc[j0][1]);
            ahi[1] = pack_h2(sc[j0][2], sc[j0][3]);
            ahi[2] = pack_h2(sc[j1][0], sc[j1][1]);
            ahi[3] = pack_h2(sc[j1][2], sc[j1][3]);
            const uint32_t ccol = (uint32_t)(2 * ks + kc) * 16u;
#pragma unroll
            for (int grp = 0; grp < 8; grp++) {
                uint32_t vh[4];
                uint32_t roff = sw128((uint32_t)(grp * 16 + (lane & 15)) * 128u + ccol);
                ldsm_x4(vh, sV[st] + roff);
                mma16816(acc[grp * 2 + 0], ahi, vh[0], vh[2]);
                mma16816(acc[grp * 2 + 1], ahi, vh[1], vh[3]);
            }
        }
        __syncthreads();
    }

    /* ---- epilogue: normalize + write fp16 into g_Ah --------------------- */
    float inv0 = 1.0f / l_i[0];
    float inv1 = 1.0f / l_i[1];
    const size_t base0 = (size_t)qr * HID;
    const size_t base1 = (size_t)(qr + 8) * HID;
#pragma unroll
    for (int t = 0; t < 16; t++) {
        int col = h * HD + t * 8 + (lane & 3) * 2;
        *(uint32_t*)(g_Ah + base0 + col) =
            pack_h2(acc[t][0] * inv0, acc[t][1] * inv0);
        *(uint32_t*)(g_Ah + base1 + col) =
            pack_h2(acc[t][2] * inv1, acc[t][3] * inv1);
    }
}

/* ------------------------------- launch ---------------------------------- */
extern "C" void kernel_launch(void* const* d_in, const int* in_sizes, int n_in,
                              void* d_out, int out_size) {
    const int*   positions = (const int*)  d_in[0];
    const float* hidden    = (const float*)d_in[1];
    const float* w_qkv     = (const float*)d_in[2];
    const float* w_o       = (const float*)d_in[3];
    float*       out       = (float*)d_out;
    (void)in_sizes; (void)n_in; (void)out_size;

    void *p_qkv = nullptr, *p_xh = nullptr, *p_ah = nullptr,
         *p_wq = nullptr, *p_wo = nullptr;
    cudaGetSymbolAddress(&p_qkv, g_qkv);
    cudaGetSymbolAddress(&p_xh,  g_Xh);
    cudaGetSymbolAddress(&p_ah,  g_Ah);
    cudaGetSymbolAddress(&p_wq,  g_Wq);
    cudaGetSymbolAddress(&p_wo,  g_Wo);

    const int gemm_smem = 4 * TILE_BYTES;   /* 64 KB */
    cudaFuncSetAttribute(gemm_mma, cudaFuncAttributeMaxDynamicSharedMemorySize,
                         gemm_smem);
    cudaFuncSetAttribute(attn_mma, cudaFuncAttributeMaxDynamicSharedMemorySize,
                         AS_TOT);

    /* 0) fp16 conversions (hi only) */
    conv_rows<<<(S_LEN * HID / 2) / 256, 256>>>(hidden, (__half*)p_xh);
    conv_wt<<<dim3(HID / 32, QKV_N / 32), dim3(32, 8)>>>(w_qkv, (__half*)p_wq, QKV_N);
    conv_wt<<<dim3(HID / 32, HID / 32), dim3(32, 8)>>>(w_o, (__half*)p_wo, HID);

    /* 1) QKV projection: 1-term fp16 (K=4096) */
    gemm_mma<<<dim3(S_LEN / 128, QKV_N / 128), 256, gemm_smem>>>(
        (const __half*)p_xh, (const __half*)p_wq, (float*)p_qkv, QKV_N);

    /* 2) RoPE -> fp16 Q/K + V fp16 transpose */
    rope_split<<<S_LEN, 256>>>(positions);

    /* 3) tensor-core flash attention (double-buffered K/V) */
    attn_mma<<<dim3(32, NQ), 256, AS_TOT>>>(positions);

    /* 4) output projection: 1-term fp16 (K=4096) */
    gemm_mma<<<dim3(S_LEN / 128, HID / 128), 256, gemm_smem>>>(
        (const __half*)p_ah, (const __half*)p_wo, out, HID);
}